// round 15
// baseline (speedup 1.0000x reference)
#include <cuda_runtime.h>
#include <cuda_bf16.h>
#include <mma.h>
#include <cstdint>

using namespace nvcuda;

#define LDB 136
#define EPAD 100096  // 782*128

__device__ float g_xji [(size_t)EPAD * 128];
__device__ float g_xkjd[(size_t)EPAD * 64];
__device__ float g_agg [(size_t)EPAD * 64];
__device__ float g_Wrbfc[768];
// bf16 hi/lo weight images, padded row-major [K][136]:
// 0 rbW1, 1 rbW2, 2 Wlin, 3 raW1a, 4 raW2a, 5 raW1b, 6 raW2b, 7 Wji, 8 Wkj, 9 Wdown(n<64)
__device__ __align__(16) __nv_bfloat16 g_Wph[10 * 128 * LDB];
__device__ __align__(16) __nv_bfloat16 g_Wpl[10 * 128 * LDB];
__device__ __align__(16) __nv_bfloat16 g_Wuph[64 * LDB];
__device__ __align__(16) __nv_bfloat16 g_Wupl[64 * LDB];
// triplet stage-1 weights: [304][16] and [48][16] bf16 hi/lo
__device__ __align__(16) __nv_bfloat16 g_Wt1h[304 * 16];
__device__ __align__(16) __nv_bfloat16 g_Wt1l[304 * 16];
__device__ __align__(16) __nv_bfloat16 g_Ws1h[48 * 16];
__device__ __align__(16) __nv_bfloat16 g_Ws1l[48 * 16];

extern __shared__ char smraw[];

typedef unsigned long long u64;

__device__ __forceinline__ float silu_(float x) { return x / (1.0f + __expf(-x)); }
__device__ __forceinline__ u64 pack2(float lo, float hi) {
    u64 d; asm("mov.b64 %0,{%1,%2};" : "=l"(d) : "r"(__float_as_uint(lo)), "r"(__float_as_uint(hi)));
    return d;
}
__device__ __forceinline__ void ffma2(u64& d, u64 a, u64 b) {
    asm("fma.rn.f32x2 %0,%1,%2,%0;" : "+l"(d) : "l"(a), "l"(b));
}
__device__ __forceinline__ float2 unpack2(u64 v) {
    unsigned lo, hi; asm("mov.b64 {%0,%1},%2;" : "=r"(lo), "=r"(hi) : "l"(v));
    return make_float2(__uint_as_float(lo), __uint_as_float(hi));
}
__device__ __forceinline__ uint32_t smem_to_u32(const void* p) {
    uint32_t a;
    asm("{ .reg .u64 t; cvta.to.shared.u64 t, %1; cvt.u32.u64 %0, t; }" : "=r"(a) : "l"(p));
    return a;
}
__device__ __forceinline__ void stsPairE(__nv_bfloat16* H, __nv_bfloat16* L, int eoff, float v0, float v1) {
    __nv_bfloat162 hp, lp;
    hp.x = __float2bfloat16(v0); hp.y = __float2bfloat16(v1);
    lp.x = __float2bfloat16(v0 - __bfloat162float(hp.x));
    lp.y = __float2bfloat16(v1 - __bfloat162float(hp.y));
    *(__nv_bfloat162*)(H + eoff) = hp;
    *(__nv_bfloat162*)(L + eoff) = lp;
}
__device__ __forceinline__ float2 ldPairE(const __nv_bfloat16* H, const __nv_bfloat16* L, int eoff) {
    __nv_bfloat162 h = *(const __nv_bfloat162*)(H + eoff);
    __nv_bfloat162 l = *(const __nv_bfloat162*)(L + eoff);
    return make_float2(__bfloat162float(h.x) + __bfloat162float(l.x),
                       __bfloat162float(h.y) + __bfloat162float(l.y));
}
template <int NT>
__device__ __forceinline__ void cpW(uint32_t whU, uint32_t wlU,
                                    const char* sh, const char* sl, int bytes, int tid) {
    for (int i = tid * 16; i < bytes; i += NT * 16) {
        asm volatile("cp.async.cg.shared.global [%0],[%1],16;" :: "r"(whU + i), "l"(sh + i) : "memory");
        asm volatile("cp.async.cg.shared.global [%0],[%1],16;" :: "r"(wlU + i), "l"(sl + i) : "memory");
    }
}
#define CP_COMMIT() asm volatile("cp.async.commit_group;" ::: "memory")
#define CP_WAIT0()  asm volatile("cp.async.wait_group 0;" ::: "memory")

// ---------------- K0a ----------------
__global__ void k_wcomb(const float* __restrict__ W1, const float* __restrict__ W2) {
    int i = blockIdx.x * blockDim.x + threadIdx.x;
    if (i < 768) {
        int r = i >> 7, c = i & 127;
        float s = 0.f;
#pragma unroll
        for (int b = 0; b < 8; b++) s += W1[r * 8 + b] * W2[b * 128 + c];
        g_Wrbfc[i] = s;
    }
}

// ---------------- K0b ----------------
__global__ void k_wprep(const float* __restrict__ rbW1, const float* __restrict__ rbW2,
                        const float* __restrict__ Wlin, const float* __restrict__ raW1,
                        const float* __restrict__ raW2, const float* __restrict__ Wup,
                        const float* __restrict__ Wji, const float* __restrict__ Wkj,
                        const float* __restrict__ Wdown) {
    int i = blockIdx.x * blockDim.x + threadIdx.x;
    const int PER = 128 * LDB;
    if (i < 10 * PER) {
        int s = i / PER, e = i - s * PER;
        int k = e / LDB, n = e - k * LDB;
        float v = 0.f;
        if (s == 9) { if (n < 64) v = Wdown[k * 64 + n]; }
        else if (n < 128) {
            const float* W = (s == 0) ? rbW1 : (s == 1) ? rbW2 : (s == 2) ? Wlin :
                             (s == 3) ? raW1 : (s == 4) ? raW2 : (s == 5) ? raW1 + 16384 :
                             (s == 6) ? raW2 + 16384 : (s == 7) ? Wji : Wkj;
            v = W[k * 128 + n];
        }
        __nv_bfloat16 h = __float2bfloat16(v);
        g_Wph[i] = h;
        g_Wpl[i] = __float2bfloat16(v - __bfloat162float(h));
    } else if (i < 10 * PER + 64 * LDB) {
        int e = i - 10 * PER;
        int k = e / LDB, n = e - k * LDB;
        float v = (n < 128) ? Wup[k * 128 + n] : 0.f;
        __nv_bfloat16 h = __float2bfloat16(v);
        g_Wuph[e] = h;
        g_Wupl[e] = __float2bfloat16(v - __bfloat162float(h));
    }
}

// ---------------- K0c ----------------
__global__ void k_wprep2(const float* __restrict__ Wt1, const float* __restrict__ Ws1) {
    int i = blockIdx.x * blockDim.x + threadIdx.x;
    if (i < 304 * 16) {
        int k = i >> 4, n = i & 15;
        float v = (k < 294 && n < 8) ? Wt1[k * 8 + n] : 0.f;
        __nv_bfloat16 h = __float2bfloat16(v);
        g_Wt1h[i] = h;
        g_Wt1l[i] = __float2bfloat16(v - __bfloat162float(h));
    } else if (i < 304 * 16 + 48 * 16) {
        int e = i - 304 * 16;
        int k = e >> 4, n = e & 15;
        float v = (k < 42 && n < 8) ? Ws1[k * 8 + n] : 0.f;
        __nv_bfloat16 h = __float2bfloat16(v);
        g_Ws1h[e] = h;
        g_Ws1l[e] = __float2bfloat16(v - __bfloat162float(h));
    }
}

// ============ shared wmma machinery (512 threads, 16 warps) ============
#define OFF_VH 0
#define OFF_VL 34816
#define OFF_TH 69632
#define OFF_TL 104448
#define OFF_WH 139264
#define OFF_WL 174080
#define OFF_F  208896
#define OFF_BS 225280
#define SM_POST (225280 + 3584)
#define SM_PRE  (225280 + 4096)

typedef wmma::fragment<wmma::accumulator, 16, 16, 16, float> AccFrag;

template <int JM>
__device__ __forceinline__ void mma_stripJ(int strip, int jbase, int ksteps,
        const __nv_bfloat16* Ah, const __nv_bfloat16* Al,
        const __nv_bfloat16* Wh, const __nv_bfloat16* Wl,
        AccFrag (&acc)[JM]) {
#pragma unroll
    for (int j = 0; j < JM; j++) wmma::fill_fragment(acc[j], 0.f);
    for (int kk = 0; kk < ksteps; kk++) {
        wmma::fragment<wmma::matrix_a, 16, 16, 16, __nv_bfloat16, wmma::row_major> ah, al;
        wmma::load_matrix_sync(ah, Ah + strip * 16 * LDB + kk * 16, LDB);
        wmma::load_matrix_sync(al, Al + strip * 16 * LDB + kk * 16, LDB);
#pragma unroll
        for (int j = 0; j < JM; j++) {
            wmma::fragment<wmma::matrix_b, 16, 16, 16, __nv_bfloat16, wmma::row_major> bh, bl;
            wmma::load_matrix_sync(bh, Wh + kk * 16 * LDB + (jbase + j) * 16, LDB);
            wmma::load_matrix_sync(bl, Wl + kk * 16 * LDB + (jbase + j) * 16, LDB);
            wmma::mma_sync(acc[j], ah, bh, acc[j]);
            wmma::mma_sync(acc[j], ah, bl, acc[j]);
            wmma::mma_sync(acc[j], al, bh, acc[j]);
        }
    }
}

// ---------------- K1: wmma edge preprocess (512 threads) ----------------
__global__ void __launch_bounds__(512, 1)
k_pre_wmma(const float* __restrict__ x1, const float* __restrict__ rbf0,
           const float* __restrict__ bji, const float* __restrict__ bkj, int E) {
    char* sm = smraw;
    __nv_bfloat16* Vh = (__nv_bfloat16*)(sm + OFF_VH);
    __nv_bfloat16* Vl = (__nv_bfloat16*)(sm + OFF_VL);
    __nv_bfloat16* Th = (__nv_bfloat16*)(sm + OFF_TH);
    __nv_bfloat16* Tl = (__nv_bfloat16*)(sm + OFF_TL);
    __nv_bfloat16* Wh = (__nv_bfloat16*)(sm + OFF_WH);
    __nv_bfloat16* Wl = (__nv_bfloat16*)(sm + OFF_WL);
    float* F   = (float*)(sm + OFF_F);
    float* bsm = (float*)(sm + OFF_BS);
    const uint32_t WhU = smem_to_u32(Wh), WlU = smem_to_u32(Wl);
    const int tid = threadIdx.x;
    const int w = tid >> 5, lane = tid & 31;
    const int strip = w >> 1, h = w & 1, jbase = h * 4;
    const int rl = lane >> 1, row = strip * 16 + rl, cb = (lane & 1) * 8;
    const int tile0 = blockIdx.x * 128;
    const int grow = tile0 + row;
    float* Fw = F + w * 256;
    const int WB = 128 * LDB * 2;

    cpW<512>(WhU, WlU, (const char*)(g_Wph + 7 * 128 * LDB), (const char*)(g_Wpl + 7 * 128 * LDB), WB, tid);
    CP_COMMIT();

    if (tid < 128) { bsm[tid] = bji[tid]; bsm[128 + tid] = bkj[tid]; }
    for (int i = tid; i < 768; i += 512) bsm[256 + i] = g_Wrbfc[i];
    {
        float4 z = make_float4(0.f, 0.f, 0.f, 0.f);
        for (int i = tid; i < 128 * 16; i += 512) {
            int r = i >> 4, c4 = (i & 15) * 4;
            *(float4*)&g_agg[(size_t)(tile0 + r) * 64 + c4] = z;
        }
    }
    {
        int r = tid >> 2, cq = (tid & 3) * 32;
        int rw = tile0 + r;
        if (rw < E) {
            const float4* xr = (const float4*)&x1[(size_t)rw * 128 + cq];
#pragma unroll
            for (int u = 0; u < 8; u++) {
                float4 v = xr[u];
                int c = cq + u * 4;
                stsPairE(Th, Tl, r * LDB + c, v.x, v.y);
                stsPairE(Th, Tl, r * LDB + c + 2, v.z, v.w);
            }
        } else {
            for (int u = 0; u < 16; u++) stsPairE(Th, Tl, r * LDB + cq + u * 2, 0.f, 0.f);
        }
    }
    float rv[6];
#pragma unroll
    for (int q = 0; q < 6; q++) rv[q] = (grow < E) ? rbf0[(size_t)grow * 6 + q] : 0.f;
    CP_WAIT0();
    __syncthreads();

    AccFrag acc[4];

    // ---- stage A ----
    mma_stripJ<4>(strip, jbase, 8, Th, Tl, Wh, Wl, acc);
    __syncthreads();
    cpW<512>(WhU, WlU, (const char*)(g_Wph + 8 * 128 * LDB), (const char*)(g_Wpl + 8 * 128 * LDB), WB, tid);
    CP_COMMIT();
    for (int j = 0; j < 4; j++) {
        wmma::store_matrix_sync(Fw, acc[j], 16, wmma::mem_row_major);
        __syncwarp();
        int col = (jbase + j) * 16 + cb;
        float v[8];
#pragma unroll
        for (int u = 0; u < 8; u++) v[u] = silu_(Fw[rl * 16 + cb + u] + bsm[col + u]);
        *(float4*)&g_xji[(size_t)grow * 128 + col]     = make_float4(v[0], v[1], v[2], v[3]);
        *(float4*)&g_xji[(size_t)grow * 128 + col + 4] = make_float4(v[4], v[5], v[6], v[7]);
        __syncwarp();
    }
    CP_WAIT0();
    __syncthreads();

    // ---- stage B ----
    mma_stripJ<4>(strip, jbase, 8, Th, Tl, Wh, Wl, acc);
    __syncthreads();
    cpW<512>(WhU, WlU, (const char*)(g_Wph + 9 * 128 * LDB), (const char*)(g_Wpl + 9 * 128 * LDB), WB, tid);
    CP_COMMIT();
    for (int j = 0; j < 4; j++) {
        wmma::store_matrix_sync(Fw, acc[j], 16, wmma::mem_row_major);
        __syncwarp();
        int col = (jbase + j) * 16 + cb;
        float v[8];
#pragma unroll
        for (int u = 0; u < 8; u++) {
            float f = 0.f;
#pragma unroll
            for (int q = 0; q < 6; q++) f += rv[q] * bsm[256 + q * 128 + col + u];
            v[u] = silu_(Fw[rl * 16 + cb + u] + bsm[128 + col + u]) * f;
        }
#pragma unroll
        for (int u = 0; u < 8; u += 2) stsPairE(Vh, Vl, row * LDB + col + u, v[u], v[u + 1]);
        __syncwarp();
    }
    CP_WAIT0();
    __syncthreads();

    // ---- stage C ----
    AccFrag ac2[2];
    mma_stripJ<2>(strip, h * 2, 8, Vh, Vl, Wh, Wl, ac2);
    for (int j = 0; j < 2; j++) {
        wmma::store_matrix_sync(Fw, ac2[j], 16, wmma::mem_row_major);
        __syncwarp();
        int col = (h * 2 + j) * 16 + cb;
        float v[8];
#pragma unroll
        for (int u = 0; u < 8; u++) v[u] = silu_(Fw[rl * 16 + cb + u]);
        *(float4*)&g_xkjd[(size_t)grow * 64 + col]     = make_float4(v[0], v[1], v[2], v[3]);
        *(float4*)&g_xkjd[(size_t)grow * 64 + col + 4] = make_float4(v[4], v[5], v[6], v[7]);
        __syncwarp();
    }
}

// ---------------- K2: persistent triplet, wmma stage-1, reg-pipelined, 3 CTA/SM ----------------
// SMEM (bytes): TH 0 (19456), TL 19456, SH 38912 (3072), SL 41984,
// WT2 45056 (2048), WS2 47104, FT0 49152, FT1 51456, FT2 53760, FS 56064 (2304 each),
// TMT 58368 (1024), TMS 59392, IK 60416 (128), IJ 60544 ; total 60672
#define SM_TRI 60672

__device__ __forceinline__ void tri_ld(const float* __restrict__ tb, const float* __restrict__ sbf,
                                       const int* __restrict__ idx_kj, const int* __restrict__ idx_ji,
                                       int t0, int T, int tid,
                                       float4 (&tbuf)[10], float4 (&sbuf)[2], int& ikr, int& ijr) {
    int nrows = T - t0; if (nrows > 32) nrows = 32;
    const float* src = tb + (size_t)t0 * 294;
    int lim = nrows * 294;
#pragma unroll
    for (int k = 0; k < 10; k++) {
        int i4 = tid + k * 256;
        float4 v = make_float4(0.f, 0.f, 0.f, 0.f);
        if (i4 < 2352) {
            int e = i4 * 4;
            if (e + 4 <= lim) v = *(const float4*)(src + e);
            else { float t[4] = {0, 0, 0, 0}; for (int j = 0; j < 4; j++) if (e + j < lim) t[j] = src[e + j]; v = make_float4(t[0], t[1], t[2], t[3]); }
        }
        tbuf[k] = v;
    }
    const float* ss = sbf + (size_t)t0 * 42;
    int lim2 = nrows * 42;
#pragma unroll
    for (int k = 0; k < 2; k++) {
        int i4 = tid + k * 256;
        float4 v = make_float4(0.f, 0.f, 0.f, 0.f);
        if (i4 < 336) {
            int e = i4 * 4;
            if (e + 4 <= lim2) v = *(const float4*)(ss + e);
            else { float t[4] = {0, 0, 0, 0}; for (int j = 0; j < 4; j++) if (e + j < lim2) t[j] = ss[e + j]; v = make_float4(t[0], t[1], t[2], t[3]); }
        }
        sbuf[k] = v;
    }
    if (tid < 32) {
        int t = t0 + tid;
        ikr = (t < T) ? idx_kj[t] : 0;
        ijr = (t < T) ? idx_ji[t] : 0;
    }
}

__global__ void __launch_bounds__(256, 3)
k_triplet(const float* __restrict__ sbf, const float* __restrict__ tb,
          const int* __restrict__ idx_kj, const int* __restrict__ idx_ji,
          const float* __restrict__ Ws2, const float* __restrict__ Wt2,
          int T, int nchunks) {
    char* sm = smraw;
    __nv_bfloat16* TH = (__nv_bfloat16*)(sm);
    __nv_bfloat16* TL = (__nv_bfloat16*)(sm + 19456);
    __nv_bfloat16* SH = (__nv_bfloat16*)(sm + 38912);
    __nv_bfloat16* SL = (__nv_bfloat16*)(sm + 41984);
    float* WT2 = (float*)(sm + 45056);
    float* WS2 = (float*)(sm + 47104);
    float* FT0 = (float*)(sm + 49152);
    float* FT1 = (float*)(sm + 51456);
    float* FT2 = (float*)(sm + 53760);
    float* FS  = (float*)(sm + 56064);
    float* TMT = (float*)(sm + 58368);
    float* TMS = (float*)(sm + 59392);
    int* IK = (int*)(sm + 60416);
    int* IJ = (int*)(sm + 60544);
    const int tid = threadIdx.x;
    const int w = tid >> 5;
    const int m = w & 1, kg = w >> 1;

    for (int i = tid; i < 11264; i += 256) ((uint32_t*)sm)[i] = 0;
    for (int i = tid; i < 512; i += 256) { WT2[i] = Wt2[i]; WS2[i] = Ws2[i]; }

    float4 tbuf[10]; float4 sbuf[2]; int ikr = 0, ijr = 0;
    int ch = blockIdx.x;
    if (ch < nchunks) tri_ld(tb, sbf, idx_kj, idx_ji, ch * 32, T, tid, tbuf, sbuf, ikr, ijr);
    __syncthreads();

    for (; ch < nchunks; ch += gridDim.x) {
        const int t0 = ch * 32;
#pragma unroll
        for (int k = 0; k < 10; k++) {
            int i4 = tid + k * 256;
            if (i4 < 2352) {
                int e = i4 * 4;
                float vv[4] = {tbuf[k].x, tbuf[k].y, tbuf[k].z, tbuf[k].w};
#pragma unroll
                for (int j = 0; j < 4; j++) {
                    int ee = e + j; int r = ee / 294, c = ee - 294 * r;
                    __nv_bfloat16 hh = __float2bfloat16(vv[j]);
                    TH[r * 304 + c] = hh;
                    TL[r * 304 + c] = __float2bfloat16(vv[j] - __bfloat162float(hh));
                }
            }
        }
#pragma unroll
        for (int k = 0; k < 2; k++) {
            int i4 = tid + k * 256;
            if (i4 < 336) {
                int e = i4 * 4;
                float vv[4] = {sbuf[k].x, sbuf[k].y, sbuf[k].z, sbuf[k].w};
#pragma unroll
                for (int j = 0; j < 4; j++) {
                    int ee = e + j; int r = ee / 42, c = ee - 42 * r;
                    __nv_bfloat16 hh = __float2bfloat16(vv[j]);
                    SH[r * 48 + c] = hh;
                    SL[r * 48 + c] = __float2bfloat16(vv[j] - __bfloat162float(hh));
                }
            }
        }
        if (tid < 32) { IK[tid] = ikr; IJ[tid] = ijr; }
        __syncthreads();
        int chn = ch + gridDim.x;
        if (chn < nchunks) tri_ld(tb, sbf, idx_kj, idx_ji, chn * 32, T, tid, tbuf, sbuf, ikr, ijr);
        {
            wmma::fragment<wmma::accumulator, 16, 16, 16, float> acc;
            wmma::fill_fragment(acc, 0.f);
            const __nv_bfloat16 *Ah, *Al, *Bh, *Bl; int lda, k0, nk; float* Fo;
            if (kg == 3) { Ah = SH + m * 16 * 48; Al = SL + m * 16 * 48; Bh = g_Ws1h; Bl = g_Ws1l; lda = 48; k0 = 0; nk = 3; Fo = FS; }
            else {
                Ah = TH + m * 16 * 304; Al = TL + m * 16 * 304; Bh = g_Wt1h; Bl = g_Wt1l; lda = 304;
                k0 = (kg == 0) ? 0 : (kg == 1) ? 7 : 13;
                nk = (kg == 0) ? 7 : 6;
                Fo = (kg == 0) ? FT0 : (kg == 1) ? FT1 : FT2;
            }
            for (int kk = k0; kk < k0 + nk; kk++) {
                wmma::fragment<wmma::matrix_a, 16, 16, 16, __nv_bfloat16, wmma::row_major> ah, al;
                wmma::fragment<wmma::matrix_b, 16, 16, 16, __nv_bfloat16, wmma::row_major> bh, bl;
                wmma::load_matrix_sync(ah, Ah + kk * 16, lda);
                wmma::load_matrix_sync(al, Al + kk * 16, lda);
                wmma::load_matrix_sync(bh, Bh + kk * 256, 16);   // global, L2-resident
                wmma::load_matrix_sync(bl, Bl + kk * 256, 16);
                wmma::mma_sync(acc, ah, bh, acc);
                wmma::mma_sync(acc, ah, bl, acc);
                wmma::mma_sync(acc, al, bh, acc);
            }
            wmma::store_matrix_sync(Fo + m * 16 * 18, acc, 18, wmma::mem_row_major);
        }
        __syncthreads();
        {
            int r = tid >> 3, c = tid & 7;
            TMT[tid] = FT0[r * 18 + c] + FT1[r * 18 + c] + FT2[r * 18 + c];
            TMS[tid] = FS[r * 18 + c];
        }
        __syncthreads();
        {
            const int tr = tid >> 3, c8 = (tid & 7) * 8;
            if (t0 + tr < T) {
                u64 tp[4] = {0, 0, 0, 0}, sp[4] = {0, 0, 0, 0};
#pragma unroll
                for (int r = 0; r < 8; r++) {
                    float at = TMT[tr * 8 + r], bs = TMS[tr * 8 + r];
                    u64 a = pack2(at, at), b = pack2(bs, bs);
                    const ulonglong2* w2 = (const ulonglong2*)(WT2 + r * 64 + c8);
                    const ulonglong2* v2 = (const ulonglong2*)(WS2 + r * 64 + c8);
                    ulonglong2 wA = w2[0], wB = w2[1], vA = v2[0], vB = v2[1];
                    ffma2(tp[0], a, wA.x); ffma2(tp[1], a, wA.y); ffma2(tp[2], a, wB.x); ffma2(tp[3], a, wB.y);
                    ffma2(sp[0], b, vA.x); ffma2(sp[1], b, vA.y); ffma2(sp[2], b, vB.x); ffma2(sp[3], b, vB.y);
                }
                size_t gk = (size_t)IK[tr] * 64 + c8;
                float4 g0 = *(const float4*)&g_xkjd[gk];
                float4 g1 = *(const float4*)&g_xkjd[gk + 4];
                float gg[8] = {g0.x, g0.y, g0.z, g0.w, g1.x, g1.y, g1.z, g1.w};
                float* dst = &g_agg[(size_t)IJ[tr] * 64 + c8];
#pragma unroll
                for (int jp = 0; jp < 4; jp++) {
                    float2 tv = unpack2(tp[jp]), sv = unpack2(sp[jp]);
                    atomicAdd(dst + 2 * jp,     tv.x * sv.x * gg[2 * jp]);
                    atomicAdd(dst + 2 * jp + 1, tv.y * sv.y * gg[2 * jp + 1]);
                }
            }
        }
        __syncthreads();
    }
}

// ---------------- K3: wmma bf16x3 edge epilogue chain (512 threads) ----------------
__global__ void __launch_bounds__(512, 1)
k_post_wmma(const float* __restrict__ x1, const float* __restrict__ rbf0,
            const float* __restrict__ Wr_g,
            const float* __restrict__ rbb1, const float* __restrict__ rbb2,
            const float* __restrict__ blin,
            const float* __restrict__ rab1, const float* __restrict__ rab2,
            float* __restrict__ out, int E) {
    char* sm = smraw;
    __nv_bfloat16* Vh = (__nv_bfloat16*)(sm + OFF_VH);
    __nv_bfloat16* Vl = (__nv_bfloat16*)(sm + OFF_VL);
    __nv_bfloat16* Th = (__nv_bfloat16*)(sm + OFF_TH);
    __nv_bfloat16* Tl = (__nv_bfloat16*)(sm + OFF_TL);
    __nv_bfloat16* Wh = (__nv_bfloat16*)(sm + OFF_WH);
    __nv_bfloat16* Wl = (__nv_bfloat16*)(sm + OFF_WL);
    float* F   = (float*)(sm + OFF_F);
    float* bsm = (float*)(sm + OFF_BS);
    const uint32_t WhU = smem_to_u32(Wh), WlU = smem_to_u32(Wl);
    const int tid = threadIdx.x;
    const int w = tid >> 5, lane = tid & 31;
    const int strip = w >> 1, h = w & 1, jbase = h * 4;
    const int rl = lane >> 1, row = strip * 16 + rl, cb = (lane & 1) * 8;
    const int tile0 = blockIdx.x * 128;
    const int grow = tile0 + row;
    float* Fw = F + w * 256;

    if (tid < 128) {
        int i = tid;
        bsm[i] = rbb1[i]; bsm[128 + i] = rbb2[i]; bsm[256 + i] = blin[i];
        bsm[384 + i] = rab1[i]; bsm[512 + i] = rab2[i];
        bsm[640 + i] = rab1[128 + i]; bsm[768 + i] = rab2[128 + i];
    }
    {
        int r = tid >> 2, cq = (tid & 3) * 16;
        const float4* ag = (const float4*)&g_agg[(size_t)(tile0 + r) * 64 + cq];
#pragma unroll
        for (int u = 0; u < 4; u++) {
            float4 v = ag[u];
            int c = cq + u * 4;
            stsPairE(Th, Tl, r * LDB + c, v.x, v.y);
            stsPairE(Th, Tl, r * LDB + c + 2, v.z, v.w);
        }
    }
    cpW<512>(WhU, WlU, (const char*)g_Wuph, (const char*)g_Wupl, 64 * LDB * 2, tid);
    CP_COMMIT(); CP_WAIT0();
    __syncthreads();

    AccFrag acc[4];
    const int WB = 128 * LDB * 2;

#define EPILOGUE(MODE, BO, DH, DL, NXT_H, NXT_L, NXT_B) do {                        \
    __syncthreads();                                                                \
    if (NXT_B) cpW<512>(WhU, WlU, (const char*)(NXT_H), (const char*)(NXT_L), NXT_B, tid); \
    CP_COMMIT();                                                                    \
    for (int j = 0; j < 4; j++) {                                                   \
        wmma::store_matrix_sync(Fw, acc[j], 16, wmma::mem_row_major);               \
        __syncwarp();                                                               \
        int col = (jbase + j) * 16 + cb;                                            \
        float d[8];                                                                 \
        _Pragma("unroll") for (int u = 0; u < 8; u++) d[u] = Fw[rl * 16 + cb + u];  \
        float v[8];                                                                 \
        if (MODE == 0) {                                                            \
            float4 x0 = *(const float4*)&g_xji[(size_t)grow * 128 + col];           \
            float4 x1v = *(const float4*)&g_xji[(size_t)grow * 128 + col + 4];      \
            float xj[8] = {x0.x, x0.y, x0.z, x0.w, x1v.x, x1v.y, x1v.z, x1v.w};     \
            _Pragma("unroll") for (int u = 0; u < 8; u++) v[u] = xj[u] + silu_(d[u]); \
        } else if (MODE == 1) {                                                     \
            _Pragma("unroll") for (int u = 0; u < 8; u++) v[u] = silu_(d[u] + bsm[(BO) + col + u]); \
        } else if (MODE == 2) {                                                     \
            _Pragma("unroll") for (int u = 0; u < 8; u += 2) {                      \
                float2 o = ldPairE(Vh, Vl, row * LDB + col + u);                    \
                v[u]     = o.x + silu_(d[u] + bsm[(BO) + col + u]);                 \
                v[u + 1] = o.y + silu_(d[u + 1] + bsm[(BO) + col + u + 1]);         \
            }                                                                       \
        } else {                                                                    \
            bool ok = grow < E;                                                     \
            float xr[8] = {0, 0, 0, 0, 0, 0, 0, 0};                                 \
            if (ok) {                                                               \
                float4 x0 = *(const float4*)&x1[(size_t)grow * 128 + col];          \
                float4 x1v = *(const float4*)&x1[(size_t)grow * 128 + col + 4];     \
                xr[0] = x0.x; xr[1] = x0.y; xr[2] = x0.z; xr[3] = x0.w;             \
                xr[4] = x1v.x; xr[5] = x1v.y; xr[6] = x1v.z; xr[7] = x1v.w;         \
            }                                                                       \
            _Pragma("unroll") for (int u = 0; u < 8; u++) v[u] = silu_(d[u] + bsm[(BO) + col + u]) + xr[u]; \
        }                                                                           \
        _Pragma("unroll") for (int u = 0; u < 8; u += 2)                            \
            stsPairE(DH, DL, row * LDB + col + u, v[u], v[u + 1]);                  \
        __syncwarp();                                                               \
    }                                                                               \
    CP_WAIT0();                                                                     \
    __syncthreads();                                                                \
} while (0)

    mma_stripJ<4>(strip, jbase, 4, Th, Tl, Wh, Wl, acc);
    EPILOGUE(0, 0, Vh, Vl, g_Wph, g_Wpl, WB);
    mma_stripJ<4>(strip, jbase, 8, Vh, Vl, Wh, Wl, acc);
    EPILOGUE(1, 0, Th, Tl, g_Wph + 128 * LDB, g_Wpl + 128 * LDB, WB);
    mma_stripJ<4>(strip, jbase, 8, Th, Tl, Wh, Wl, acc);
    EPILOGUE(2, 128, Vh, Vl, g_Wph + 2 * 128 * LDB, g_Wpl + 2 * 128 * LDB, WB);
    mma_stripJ<4>(strip, jbase, 8, Vh, Vl, Wh, Wl, acc);
    EPILOGUE(3, 256, Vh, Vl, g_Wph + 3 * 128 * LDB, g_Wpl + 3 * 128 * LDB, WB);
    mma_stripJ<4>(strip, jbase, 8, Vh, Vl, Wh, Wl, acc);
    EPILOGUE(1, 384, Th, Tl, g_Wph + 4 * 128 * LDB, g_Wpl + 4 * 128 * LDB, WB);
    mma_stripJ<4>(strip, jbase, 8, Th, Tl, Wh, Wl, acc);
    EPILOGUE(2, 512, Vh, Vl, g_Wph + 5 * 128 * LDB, g_Wpl + 5 * 128 * LDB, WB);
    mma_stripJ<4>(strip, jbase, 8, Vh, Vl, Wh, Wl, acc);
    EPILOGUE(1, 640, Th, Tl, g_Wph + 6 * 128 * LDB, g_Wpl + 6 * 128 * LDB, WB);
    mma_stripJ<4>(strip, jbase, 8, Th, Tl, Wh, Wl, acc);
    EPILOGUE(2, 768, Vh, Vl, (const __nv_bfloat16*)0, (const __nv_bfloat16*)0, 0);

    for (int i = tid; i < 768; i += 512) F[i] = Wr_g[i];
    for (int i = tid; i < 768; i += 512) {
        int r = i / 6, q = i - 6 * r;
        int rw = tile0 + r;
        F[768 + i] = (rw < E) ? rbf0[(size_t)rw * 6 + q] : 0.f;
    }
    __syncthreads();

    for (int i = tid; i < 128 * 32; i += 512) {
        int rr = i >> 5, cbl = (i & 31) * 4;
        int gr = tile0 + rr;
        if (gr >= E) continue;
        float2 p0 = ldPairE(Vh, Vl, rr * LDB + cbl);
        float2 p1 = ldPairE(Vh, Vl, rr * LDB + cbl + 2);
        float rv[6];
#pragma unroll
        for (int q = 0; q < 6; q++) rv[q] = F[768 + rr * 6 + q];
        float e1v[4] = {p0.x, p0.y, p1.x, p1.y};
        float e2v[4];
#pragma unroll
        for (int u = 0; u < 4; u++) {
            float f = 0.f;
#pragma unroll
            for (int q = 0; q < 6; q++) f += rv[q] * F[q * 128 + cbl + u];
            e2v[u] = f * e1v[u];
        }
        *(float4*)&out[(size_t)gr * 128 + cbl] = make_float4(e1v[0], e1v[1], e1v[2], e1v[3]);
        *(float4*)&out[((size_t)E + gr) * 128 + cbl] = make_float4(e2v[0], e2v[1], e2v[2], e2v[3]);
    }
}

extern "C" void kernel_launch(void* const* d_in, const int* in_sizes, int n_in,
                              void* d_out, int out_size) {
    const float* x1    = (const float*)d_in[0];
    const float* rbf0  = (const float*)d_in[1];
    const float* sbf   = (const float*)d_in[2];
    const float* tb    = (const float*)d_in[3];
    const int* idx_kj  = (const int*)d_in[4];
    const int* idx_ji  = (const int*)d_in[5];
    const float* W_rbf1 = (const float*)d_in[6];
    const float* W_rbf2 = (const float*)d_in[7];
    const float* W_sbf1 = (const float*)d_in[8];
    const float* W_sbf2 = (const float*)d_in[9];
    const float* W_t1   = (const float*)d_in[10];
    const float* W_t2   = (const float*)d_in[11];
    const float* W_rbf  = (const float*)d_in[12];
    const float* W_kj   = (const float*)d_in[13];
    const float* b_kj   = (const float*)d_in[14];
    const float* W_ji   = (const float*)d_in[15];
    const float* b_ji   = (const float*)d_in[16];
    const float* W_down = (const float*)d_in[17];
    const float* W_up   = (const float*)d_in[18];
    const float* rbW1   = (const float*)d_in[19];
    const float* rbb1   = (const float*)d_in[20];
    const float* rbW2   = (const float*)d_in[21];
    const float* rbb2   = (const float*)d_in[22];
    const float* W_lin  = (const float*)d_in[23];
    const float* b_lin  = (const float*)d_in[24];
    const float* raW1   = (const float*)d_in[25];
    const float* rab1   = (const float*)d_in[26];
    const float* raW2   = (const float*)d_in[27];
    const float* rab2   = (const float*)d_in[28];
    float* out = (float*)d_out;

    const int E = in_sizes[0] / 128;
    const int T = in_sizes[4];
    const int etiles = (E + 127) / 128;
    const int nchunks = (T + 31) / 32;
    const int nprep = 10 * 128 * LDB + 64 * LDB;
    const int nprep2 = 304 * 16 + 48 * 16;

    cudaFuncSetAttribute(k_pre_wmma,  cudaFuncAttributeMaxDynamicSharedMemorySize, SM_PRE);
    cudaFuncSetAttribute(k_triplet,   cudaFuncAttributeMaxDynamicSharedMemorySize, SM_TRI);
    cudaFuncSetAttribute(k_post_wmma, cudaFuncAttributeMaxDynamicSharedMemorySize, SM_POST);

    k_wcomb<<<3, 256>>>(W_rbf1, W_rbf2);
    k_wprep<<<(nprep + 255) / 256, 256>>>(rbW1, rbW2, W_lin, raW1, raW2, W_up, W_ji, W_kj, W_down);
    k_wprep2<<<(nprep2 + 255) / 256, 256>>>(W_t1, W_sbf1);
    k_pre_wmma<<<etiles, 512, SM_PRE>>>(x1, rbf0, b_ji, b_kj, E);
    k_triplet<<<444, 256, SM_TRI>>>(sbf, tb, idx_kj, idx_ji, W_sbf2, W_t2, T, nchunks);
    k_post_wmma<<<etiles, 512, SM_POST>>>(x1, rbf0, W_rbf, rbb1, rbb2, b_lin, rab1, rab2, out, E);
}

// round 16
// speedup vs baseline: 1.1568x; 1.1568x over previous
#include <cuda_runtime.h>
#include <cuda_bf16.h>
#include <mma.h>
#include <cstdint>

using namespace nvcuda;

#define LDB 136
#define EPAD 100096  // 782*128

__device__ float g_xji [(size_t)EPAD * 128];
__device__ float g_xkjd[(size_t)EPAD * 64];
__device__ float g_agg [(size_t)EPAD * 64];
__device__ float g_Wrbfc[768];
// bf16 hi/lo weight images, padded row-major [K][136]:
// 0 rbW1, 1 rbW2, 2 Wlin, 3 raW1a, 4 raW2a, 5 raW1b, 6 raW2b, 7 Wji, 8 Wkj, 9 Wdown(n<64)
__device__ __align__(16) __nv_bfloat16 g_Wph[10 * 128 * LDB];
__device__ __align__(16) __nv_bfloat16 g_Wpl[10 * 128 * LDB];
__device__ __align__(16) __nv_bfloat16 g_Wuph[64 * LDB];
__device__ __align__(16) __nv_bfloat16 g_Wupl[64 * LDB];
// triplet stage-1 weights: [304][16] and [48][16] bf16 hi/lo
__device__ __align__(16) __nv_bfloat16 g_Wt1h[304 * 16];
__device__ __align__(16) __nv_bfloat16 g_Wt1l[304 * 16];
__device__ __align__(16) __nv_bfloat16 g_Ws1h[48 * 16];
__device__ __align__(16) __nv_bfloat16 g_Ws1l[48 * 16];

extern __shared__ char smraw[];

typedef unsigned long long u64;

__device__ __forceinline__ float silu_(float x) { return x / (1.0f + __expf(-x)); }
__device__ __forceinline__ u64 pack2(float lo, float hi) {
    u64 d; asm("mov.b64 %0,{%1,%2};" : "=l"(d) : "r"(__float_as_uint(lo)), "r"(__float_as_uint(hi)));
    return d;
}
__device__ __forceinline__ void ffma2(u64& d, u64 a, u64 b) {
    asm("fma.rn.f32x2 %0,%1,%2,%0;" : "+l"(d) : "l"(a), "l"(b));
}
__device__ __forceinline__ float2 unpack2(u64 v) {
    unsigned lo, hi; asm("mov.b64 {%0,%1},%2;" : "=r"(lo), "=r"(hi) : "l"(v));
    return make_float2(__uint_as_float(lo), __uint_as_float(hi));
}
__device__ __forceinline__ uint32_t smem_to_u32(const void* p) {
    uint32_t a;
    asm("{ .reg .u64 t; cvta.to.shared.u64 t, %1; cvt.u32.u64 %0, t; }" : "=r"(a) : "l"(p));
    return a;
}
__device__ __forceinline__ void stsPairE(__nv_bfloat16* H, __nv_bfloat16* L, int eoff, float v0, float v1) {
    __nv_bfloat162 hp, lp;
    hp.x = __float2bfloat16(v0); hp.y = __float2bfloat16(v1);
    lp.x = __float2bfloat16(v0 - __bfloat162float(hp.x));
    lp.y = __float2bfloat16(v1 - __bfloat162float(hp.y));
    *(__nv_bfloat162*)(H + eoff) = hp;
    *(__nv_bfloat162*)(L + eoff) = lp;
}
__device__ __forceinline__ float2 ldPairE(const __nv_bfloat16* H, const __nv_bfloat16* L, int eoff) {
    __nv_bfloat162 h = *(const __nv_bfloat162*)(H + eoff);
    __nv_bfloat162 l = *(const __nv_bfloat162*)(L + eoff);
    return make_float2(__bfloat162float(h.x) + __bfloat162float(l.x),
                       __bfloat162float(h.y) + __bfloat162float(l.y));
}
__device__ __forceinline__ void redg4(float* dst, float a, float b, float c, float d) {
    asm volatile("red.global.add.v4.f32 [%0], {%1, %2, %3, %4};"
                 :: "l"(dst), "f"(a), "f"(b), "f"(c), "f"(d) : "memory");
}
template <int NT>
__device__ __forceinline__ void cpW(uint32_t whU, uint32_t wlU,
                                    const char* sh, const char* sl, int bytes, int tid) {
    for (int i = tid * 16; i < bytes; i += NT * 16) {
        asm volatile("cp.async.cg.shared.global [%0],[%1],16;" :: "r"(whU + i), "l"(sh + i) : "memory");
        asm volatile("cp.async.cg.shared.global [%0],[%1],16;" :: "r"(wlU + i), "l"(sl + i) : "memory");
    }
}
#define CP_COMMIT() asm volatile("cp.async.commit_group;" ::: "memory")
#define CP_WAIT0()  asm volatile("cp.async.wait_group 0;" ::: "memory")

// ---------------- K0a ----------------
__global__ void k_wcomb(const float* __restrict__ W1, const float* __restrict__ W2) {
    int i = blockIdx.x * blockDim.x + threadIdx.x;
    if (i < 768) {
        int r = i >> 7, c = i & 127;
        float s = 0.f;
#pragma unroll
        for (int b = 0; b < 8; b++) s += W1[r * 8 + b] * W2[b * 128 + c];
        g_Wrbfc[i] = s;
    }
}

// ---------------- K0b ----------------
__global__ void k_wprep(const float* __restrict__ rbW1, const float* __restrict__ rbW2,
                        const float* __restrict__ Wlin, const float* __restrict__ raW1,
                        const float* __restrict__ raW2, const float* __restrict__ Wup,
                        const float* __restrict__ Wji, const float* __restrict__ Wkj,
                        const float* __restrict__ Wdown) {
    int i = blockIdx.x * blockDim.x + threadIdx.x;
    const int PER = 128 * LDB;
    if (i < 10 * PER) {
        int s = i / PER, e = i - s * PER;
        int k = e / LDB, n = e - k * LDB;
        float v = 0.f;
        if (s == 9) { if (n < 64) v = Wdown[k * 64 + n]; }
        else if (n < 128) {
            const float* W = (s == 0) ? rbW1 : (s == 1) ? rbW2 : (s == 2) ? Wlin :
                             (s == 3) ? raW1 : (s == 4) ? raW2 : (s == 5) ? raW1 + 16384 :
                             (s == 6) ? raW2 + 16384 : (s == 7) ? Wji : Wkj;
            v = W[k * 128 + n];
        }
        __nv_bfloat16 h = __float2bfloat16(v);
        g_Wph[i] = h;
        g_Wpl[i] = __float2bfloat16(v - __bfloat162float(h));
    } else if (i < 10 * PER + 64 * LDB) {
        int e = i - 10 * PER;
        int k = e / LDB, n = e - k * LDB;
        float v = (n < 128) ? Wup[k * 128 + n] : 0.f;
        __nv_bfloat16 h = __float2bfloat16(v);
        g_Wuph[e] = h;
        g_Wupl[e] = __float2bfloat16(v - __bfloat162float(h));
    }
}

// ---------------- K0c ----------------
__global__ void k_wprep2(const float* __restrict__ Wt1, const float* __restrict__ Ws1) {
    int i = blockIdx.x * blockDim.x + threadIdx.x;
    if (i < 304 * 16) {
        int k = i >> 4, n = i & 15;
        float v = (k < 294 && n < 8) ? Wt1[k * 8 + n] : 0.f;
        __nv_bfloat16 h = __float2bfloat16(v);
        g_Wt1h[i] = h;
        g_Wt1l[i] = __float2bfloat16(v - __bfloat162float(h));
    } else if (i < 304 * 16 + 48 * 16) {
        int e = i - 304 * 16;
        int k = e >> 4, n = e & 15;
        float v = (k < 42 && n < 8) ? Ws1[k * 8 + n] : 0.f;
        __nv_bfloat16 h = __float2bfloat16(v);
        g_Ws1h[e] = h;
        g_Ws1l[e] = __float2bfloat16(v - __bfloat162float(h));
    }
}

// ============ shared wmma machinery (512 threads, 16 warps) ============
#define OFF_VH 0
#define OFF_VL 34816
#define OFF_TH 69632
#define OFF_TL 104448
#define OFF_WH 139264
#define OFF_WL 174080
#define OFF_F  208896
#define OFF_BS 225280
#define SM_POST (225280 + 3584)
#define SM_PRE  (225280 + 4096)

typedef wmma::fragment<wmma::accumulator, 16, 16, 16, float> AccFrag;

template <int JM>
__device__ __forceinline__ void mma_stripJ(int strip, int jbase, int ksteps,
        const __nv_bfloat16* Ah, const __nv_bfloat16* Al,
        const __nv_bfloat16* Wh, const __nv_bfloat16* Wl,
        AccFrag (&acc)[JM]) {
#pragma unroll
    for (int j = 0; j < JM; j++) wmma::fill_fragment(acc[j], 0.f);
    for (int kk = 0; kk < ksteps; kk++) {
        wmma::fragment<wmma::matrix_a, 16, 16, 16, __nv_bfloat16, wmma::row_major> ah, al;
        wmma::load_matrix_sync(ah, Ah + strip * 16 * LDB + kk * 16, LDB);
        wmma::load_matrix_sync(al, Al + strip * 16 * LDB + kk * 16, LDB);
#pragma unroll
        for (int j = 0; j < JM; j++) {
            wmma::fragment<wmma::matrix_b, 16, 16, 16, __nv_bfloat16, wmma::row_major> bh, bl;
            wmma::load_matrix_sync(bh, Wh + kk * 16 * LDB + (jbase + j) * 16, LDB);
            wmma::load_matrix_sync(bl, Wl + kk * 16 * LDB + (jbase + j) * 16, LDB);
            wmma::mma_sync(acc[j], ah, bh, acc[j]);
            wmma::mma_sync(acc[j], ah, bl, acc[j]);
            wmma::mma_sync(acc[j], al, bh, acc[j]);
        }
    }
}

// ---------------- K1: wmma edge preprocess (512 threads) ----------------
__global__ void __launch_bounds__(512, 1)
k_pre_wmma(const float* __restrict__ x1, const float* __restrict__ rbf0,
           const float* __restrict__ bji, const float* __restrict__ bkj, int E) {
    char* sm = smraw;
    __nv_bfloat16* Vh = (__nv_bfloat16*)(sm + OFF_VH);
    __nv_bfloat16* Vl = (__nv_bfloat16*)(sm + OFF_VL);
    __nv_bfloat16* Th = (__nv_bfloat16*)(sm + OFF_TH);
    __nv_bfloat16* Tl = (__nv_bfloat16*)(sm + OFF_TL);
    __nv_bfloat16* Wh = (__nv_bfloat16*)(sm + OFF_WH);
    __nv_bfloat16* Wl = (__nv_bfloat16*)(sm + OFF_WL);
    float* F   = (float*)(sm + OFF_F);
    float* bsm = (float*)(sm + OFF_BS);
    const uint32_t WhU = smem_to_u32(Wh), WlU = smem_to_u32(Wl);
    const int tid = threadIdx.x;
    const int w = tid >> 5, lane = tid & 31;
    const int strip = w >> 1, h = w & 1, jbase = h * 4;
    const int rl = lane >> 1, row = strip * 16 + rl, cb = (lane & 1) * 8;
    const int tile0 = blockIdx.x * 128;
    const int grow = tile0 + row;
    float* Fw = F + w * 256;
    const int WB = 128 * LDB * 2;

    cpW<512>(WhU, WlU, (const char*)(g_Wph + 7 * 128 * LDB), (const char*)(g_Wpl + 7 * 128 * LDB), WB, tid);
    CP_COMMIT();

    if (tid < 128) { bsm[tid] = bji[tid]; bsm[128 + tid] = bkj[tid]; }
    for (int i = tid; i < 768; i += 512) bsm[256 + i] = g_Wrbfc[i];
    {
        float4 z = make_float4(0.f, 0.f, 0.f, 0.f);
        for (int i = tid; i < 128 * 16; i += 512) {
            int r = i >> 4, c4 = (i & 15) * 4;
            *(float4*)&g_agg[(size_t)(tile0 + r) * 64 + c4] = z;
        }
    }
    {
        int r = tid >> 2, cq = (tid & 3) * 32;
        int rw = tile0 + r;
        if (rw < E) {
            const float4* xr = (const float4*)&x1[(size_t)rw * 128 + cq];
#pragma unroll
            for (int u = 0; u < 8; u++) {
                float4 v = xr[u];
                int c = cq + u * 4;
                stsPairE(Th, Tl, r * LDB + c, v.x, v.y);
                stsPairE(Th, Tl, r * LDB + c + 2, v.z, v.w);
            }
        } else {
            for (int u = 0; u < 16; u++) stsPairE(Th, Tl, r * LDB + cq + u * 2, 0.f, 0.f);
        }
    }
    float rv[6];
#pragma unroll
    for (int q = 0; q < 6; q++) rv[q] = (grow < E) ? rbf0[(size_t)grow * 6 + q] : 0.f;
    CP_WAIT0();
    __syncthreads();

    AccFrag acc[4];

    // ---- stage A ----
    mma_stripJ<4>(strip, jbase, 8, Th, Tl, Wh, Wl, acc);
    __syncthreads();
    cpW<512>(WhU, WlU, (const char*)(g_Wph + 8 * 128 * LDB), (const char*)(g_Wpl + 8 * 128 * LDB), WB, tid);
    CP_COMMIT();
    for (int j = 0; j < 4; j++) {
        wmma::store_matrix_sync(Fw, acc[j], 16, wmma::mem_row_major);
        __syncwarp();
        int col = (jbase + j) * 16 + cb;
        float v[8];
#pragma unroll
        for (int u = 0; u < 8; u++) v[u] = silu_(Fw[rl * 16 + cb + u] + bsm[col + u]);
        *(float4*)&g_xji[(size_t)grow * 128 + col]     = make_float4(v[0], v[1], v[2], v[3]);
        *(float4*)&g_xji[(size_t)grow * 128 + col + 4] = make_float4(v[4], v[5], v[6], v[7]);
        __syncwarp();
    }
    CP_WAIT0();
    __syncthreads();

    // ---- stage B ----
    mma_stripJ<4>(strip, jbase, 8, Th, Tl, Wh, Wl, acc);
    __syncthreads();
    cpW<512>(WhU, WlU, (const char*)(g_Wph + 9 * 128 * LDB), (const char*)(g_Wpl + 9 * 128 * LDB), WB, tid);
    CP_COMMIT();
    for (int j = 0; j < 4; j++) {
        wmma::store_matrix_sync(Fw, acc[j], 16, wmma::mem_row_major);
        __syncwarp();
        int col = (jbase + j) * 16 + cb;
        float v[8];
#pragma unroll
        for (int u = 0; u < 8; u++) {
            float f = 0.f;
#pragma unroll
            for (int q = 0; q < 6; q++) f += rv[q] * bsm[256 + q * 128 + col + u];
            v[u] = silu_(Fw[rl * 16 + cb + u] + bsm[128 + col + u]) * f;
        }
#pragma unroll
        for (int u = 0; u < 8; u += 2) stsPairE(Vh, Vl, row * LDB + col + u, v[u], v[u + 1]);
        __syncwarp();
    }
    CP_WAIT0();
    __syncthreads();

    // ---- stage C ----
    AccFrag ac2[2];
    mma_stripJ<2>(strip, h * 2, 8, Vh, Vl, Wh, Wl, ac2);
    for (int j = 0; j < 2; j++) {
        wmma::store_matrix_sync(Fw, ac2[j], 16, wmma::mem_row_major);
        __syncwarp();
        int col = (h * 2 + j) * 16 + cb;
        float v[8];
#pragma unroll
        for (int u = 0; u < 8; u++) v[u] = silu_(Fw[rl * 16 + cb + u]);
        *(float4*)&g_xkjd[(size_t)grow * 64 + col]     = make_float4(v[0], v[1], v[2], v[3]);
        *(float4*)&g_xkjd[(size_t)grow * 64 + col + 4] = make_float4(v[4], v[5], v[6], v[7]);
        __syncwarp();
    }
}

// ---------------- K2: persistent triplet, wmma stage-1, reg-pipelined (R13) ----------------
#define SM_TRI 83200

__device__ __forceinline__ void tri_ld(const float* __restrict__ tb, const float* __restrict__ sbf,
                                       const int* __restrict__ idx_kj, const int* __restrict__ idx_ji,
                                       int t0, int T, int tid,
                                       float4 (&tbuf)[10], float4 (&sbuf)[2], int& ikr, int& ijr) {
    int nrows = T - t0; if (nrows > 32) nrows = 32;
    const float* src = tb + (size_t)t0 * 294;
    int lim = nrows * 294;
#pragma unroll
    for (int k = 0; k < 10; k++) {
        int i4 = tid + k * 256;
        float4 v = make_float4(0.f, 0.f, 0.f, 0.f);
        if (i4 < 2352) {
            int e = i4 * 4;
            if (e + 4 <= lim) v = *(const float4*)(src + e);
            else { float t[4] = {0, 0, 0, 0}; for (int j = 0; j < 4; j++) if (e + j < lim) t[j] = src[e + j]; v = make_float4(t[0], t[1], t[2], t[3]); }
        }
        tbuf[k] = v;
    }
    const float* ss = sbf + (size_t)t0 * 42;
    int lim2 = nrows * 42;
#pragma unroll
    for (int k = 0; k < 2; k++) {
        int i4 = tid + k * 256;
        float4 v = make_float4(0.f, 0.f, 0.f, 0.f);
        if (i4 < 336) {
            int e = i4 * 4;
            if (e + 4 <= lim2) v = *(const float4*)(ss + e);
            else { float t[4] = {0, 0, 0, 0}; for (int j = 0; j < 4; j++) if (e + j < lim2) t[j] = ss[e + j]; v = make_float4(t[0], t[1], t[2], t[3]); }
        }
        sbuf[k] = v;
    }
    if (tid < 32) {
        int t = t0 + tid;
        ikr = (t < T) ? idx_kj[t] : 0;
        ijr = (t < T) ? idx_ji[t] : 0;
    }
}

__global__ void __launch_bounds__(256, 2)
k_triplet(const float* __restrict__ sbf, const float* __restrict__ tb,
          const int* __restrict__ idx_kj, const int* __restrict__ idx_ji,
          const float* __restrict__ Ws2, const float* __restrict__ Wt2,
          int T, int nchunks) {
    char* sm = smraw;
    __nv_bfloat16* TH = (__nv_bfloat16*)(sm);
    __nv_bfloat16* TL = (__nv_bfloat16*)(sm + 19456);
    __nv_bfloat16* SH = (__nv_bfloat16*)(sm + 38912);
    __nv_bfloat16* SL = (__nv_bfloat16*)(sm + 41984);
    __nv_bfloat16* W1H = (__nv_bfloat16*)(sm + 45056);
    __nv_bfloat16* W1L = (__nv_bfloat16*)(sm + 54784);
    __nv_bfloat16* S1H = (__nv_bfloat16*)(sm + 64512);
    __nv_bfloat16* S1L = (__nv_bfloat16*)(sm + 66048);
    float* WT2 = (float*)(sm + 67584);
    float* WS2 = (float*)(sm + 69632);
    float* FT0 = (float*)(sm + 71680);
    float* FT1 = (float*)(sm + 73984);
    float* FT2 = (float*)(sm + 76288);
    float* FS  = (float*)(sm + 78592);
    float* TMT = (float*)(sm + 80896);
    float* TMS = (float*)(sm + 81920);
    int* IK = (int*)(sm + 82944);
    int* IJ = (int*)(sm + 83072);
    const int tid = threadIdx.x;
    const int w = tid >> 5;
    const int m = w & 1, kg = w >> 1;

    for (int i = tid; i < 11264; i += 256) ((uint32_t*)sm)[i] = 0;
    for (int i = tid; i < 2432; i += 256) {
        ((uint32_t*)W1H)[i] = ((const uint32_t*)g_Wt1h)[i];
        ((uint32_t*)W1L)[i] = ((const uint32_t*)g_Wt1l)[i];
    }
    for (int i = tid; i < 384; i += 256) {
        ((uint32_t*)S1H)[i] = ((const uint32_t*)g_Ws1h)[i];
        ((uint32_t*)S1L)[i] = ((const uint32_t*)g_Ws1l)[i];
    }
    for (int i = tid; i < 512; i += 256) { WT2[i] = Wt2[i]; WS2[i] = Ws2[i]; }

    float4 tbuf[10]; float4 sbuf[2]; int ikr = 0, ijr = 0;
    int ch = blockIdx.x;
    if (ch < nchunks) tri_ld(tb, sbf, idx_kj, idx_ji, ch * 32, T, tid, tbuf, sbuf, ikr, ijr);
    __syncthreads();

    for (; ch < nchunks; ch += gridDim.x) {
        const int t0 = ch * 32;
#pragma unroll
        for (int k = 0; k < 10; k++) {
            int i4 = tid + k * 256;
            if (i4 < 2352) {
                int e = i4 * 4;
                float vv[4] = {tbuf[k].x, tbuf[k].y, tbuf[k].z, tbuf[k].w};
#pragma unroll
                for (int j = 0; j < 4; j++) {
                    int ee = e + j; int r = ee / 294, c = ee - 294 * r;
                    __nv_bfloat16 hh = __float2bfloat16(vv[j]);
                    TH[r * 304 + c] = hh;
                    TL[r * 304 + c] = __float2bfloat16(vv[j] - __bfloat162float(hh));
                }
            }
        }
#pragma unroll
        for (int k = 0; k < 2; k++) {
            int i4 = tid + k * 256;
            if (i4 < 336) {
                int e = i4 * 4;
                float vv[4] = {sbuf[k].x, sbuf[k].y, sbuf[k].z, sbuf[k].w};
#pragma unroll
                for (int j = 0; j < 4; j++) {
                    int ee = e + j; int r = ee / 42, c = ee - 42 * r;
                    __nv_bfloat16 hh = __float2bfloat16(vv[j]);
                    SH[r * 48 + c] = hh;
                    SL[r * 48 + c] = __float2bfloat16(vv[j] - __bfloat162float(hh));
                }
            }
        }
        if (tid < 32) { IK[tid] = ikr; IJ[tid] = ijr; }
        __syncthreads();
        int chn = ch + gridDim.x;
        if (chn < nchunks) tri_ld(tb, sbf, idx_kj, idx_ji, chn * 32, T, tid, tbuf, sbuf, ikr, ijr);
        {
            wmma::fragment<wmma::accumulator, 16, 16, 16, float> acc;
            wmma::fill_fragment(acc, 0.f);
            const __nv_bfloat16 *Ah, *Al, *Bh, *Bl; int lda, k0, nk; float* Fo;
            if (kg == 3) { Ah = SH + m * 16 * 48; Al = SL + m * 16 * 48; Bh = S1H; Bl = S1L; lda = 48; k0 = 0; nk = 3; Fo = FS; }
            else {
                Ah = TH + m * 16 * 304; Al = TL + m * 16 * 304; Bh = W1H; Bl = W1L; lda = 304;
                k0 = (kg == 0) ? 0 : (kg == 1) ? 7 : 13;
                nk = (kg == 0) ? 7 : 6;
                Fo = (kg == 0) ? FT0 : (kg == 1) ? FT1 : FT2;
            }
            for (int kk = k0; kk < k0 + nk; kk++) {
                wmma::fragment<wmma::matrix_a, 16, 16, 16, __nv_bfloat16, wmma::row_major> ah, al;
                wmma::fragment<wmma::matrix_b, 16, 16, 16, __nv_bfloat16, wmma::row_major> bh, bl;
                wmma::load_matrix_sync(ah, Ah + kk * 16, lda);
                wmma::load_matrix_sync(al, Al + kk * 16, lda);
                wmma::load_matrix_sync(bh, Bh + kk * 256, 16);
                wmma::load_matrix_sync(bl, Bl + kk * 256, 16);
                wmma::mma_sync(acc, ah, bh, acc);
                wmma::mma_sync(acc, ah, bl, acc);
                wmma::mma_sync(acc, al, bh, acc);
            }
            wmma::store_matrix_sync(Fo + m * 16 * 18, acc, 18, wmma::mem_row_major);
        }
        __syncthreads();
        {
            int r = tid >> 3, c = tid & 7;
            TMT[tid] = FT0[r * 18 + c] + FT1[r * 18 + c] + FT2[r * 18 + c];
            TMS[tid] = FS[r * 18 + c];
        }
        __syncthreads();
        {
            const int tr = tid >> 3, c8 = (tid & 7) * 8;
            if (t0 + tr < T) {
                u64 tp[4] = {0, 0, 0, 0}, sp[4] = {0, 0, 0, 0};
#pragma unroll
                for (int r = 0; r < 8; r++) {
                    float at = TMT[tr * 8 + r], bs = TMS[tr * 8 + r];
                    u64 a = pack2(at, at), b = pack2(bs, bs);
                    const ulonglong2* w2 = (const ulonglong2*)(WT2 + r * 64 + c8);
                    const ulonglong2* v2 = (const ulonglong2*)(WS2 + r * 64 + c8);
                    ulonglong2 wA = w2[0], wB = w2[1], vA = v2[0], vB = v2[1];
                    ffma2(tp[0], a, wA.x); ffma2(tp[1], a, wA.y); ffma2(tp[2], a, wB.x); ffma2(tp[3], a, wB.y);
                    ffma2(sp[0], b, vA.x); ffma2(sp[1], b, vA.y); ffma2(sp[2], b, vB.x); ffma2(sp[3], b, vB.y);
                }
                size_t gk = (size_t)IK[tr] * 64 + c8;
                float4 g0 = *(const float4*)&g_xkjd[gk];
                float4 g1 = *(const float4*)&g_xkjd[gk + 4];
                float* dst = &g_agg[(size_t)IJ[tr] * 64 + c8];
                float2 t0v = unpack2(tp[0]), t1v = unpack2(tp[1]), t2v = unpack2(tp[2]), t3v = unpack2(tp[3]);
                float2 s0v = unpack2(sp[0]), s1v = unpack2(sp[1]), s2v = unpack2(sp[2]), s3v = unpack2(sp[3]);
                redg4(dst,     t0v.x * s0v.x * g0.x, t0v.y * s0v.y * g0.y,
                               t1v.x * s1v.x * g0.z, t1v.y * s1v.y * g0.w);
                redg4(dst + 4, t2v.x * s2v.x * g1.x, t2v.y * s2v.y * g1.y,
                               t3v.x * s3v.x * g1.z, t3v.y * s3v.y * g1.w);
            }
        }
        __syncthreads();
    }
}

// ---------------- K3: wmma bf16x3 edge epilogue chain (512 threads) ----------------
__global__ void __launch_bounds__(512, 1)
k_post_wmma(const float* __restrict__ x1, const float* __restrict__ rbf0,
            const float* __restrict__ Wr_g,
            const float* __restrict__ rbb1, const float* __restrict__ rbb2,
            const float* __restrict__ blin,
            const float* __restrict__ rab1, const float* __restrict__ rab2,
            float* __restrict__ out, int E) {
    char* sm = smraw;
    __nv_bfloat16* Vh = (__nv_bfloat16*)(sm + OFF_VH);
    __nv_bfloat16* Vl = (__nv_bfloat16*)(sm + OFF_VL);
    __nv_bfloat16* Th = (__nv_bfloat16*)(sm + OFF_TH);
    __nv_bfloat16* Tl = (__nv_bfloat16*)(sm + OFF_TL);
    __nv_bfloat16* Wh = (__nv_bfloat16*)(sm + OFF_WH);
    __nv_bfloat16* Wl = (__nv_bfloat16*)(sm + OFF_WL);
    float* F   = (float*)(sm + OFF_F);
    float* bsm = (float*)(sm + OFF_BS);
    const uint32_t WhU = smem_to_u32(Wh), WlU = smem_to_u32(Wl);
    const int tid = threadIdx.x;
    const int w = tid >> 5, lane = tid & 31;
    const int strip = w >> 1, h = w & 1, jbase = h * 4;
    const int rl = lane >> 1, row = strip * 16 + rl, cb = (lane & 1) * 8;
    const int tile0 = blockIdx.x * 128;
    const int grow = tile0 + row;
    float* Fw = F + w * 256;

    if (tid < 128) {
        int i = tid;
        bsm[i] = rbb1[i]; bsm[128 + i] = rbb2[i]; bsm[256 + i] = blin[i];
        bsm[384 + i] = rab1[i]; bsm[512 + i] = rab2[i];
        bsm[640 + i] = rab1[128 + i]; bsm[768 + i] = rab2[128 + i];
    }
    {
        int r = tid >> 2, cq = (tid & 3) * 16;
        const float4* ag = (const float4*)&g_agg[(size_t)(tile0 + r) * 64 + cq];
#pragma unroll
        for (int u = 0; u < 4; u++) {
            float4 v = ag[u];
            int c = cq + u * 4;
            stsPairE(Th, Tl, r * LDB + c, v.x, v.y);
            stsPairE(Th, Tl, r * LDB + c + 2, v.z, v.w);
        }
    }
    cpW<512>(WhU, WlU, (const char*)g_Wuph, (const char*)g_Wupl, 64 * LDB * 2, tid);
    CP_COMMIT(); CP_WAIT0();
    __syncthreads();

    AccFrag acc[4];
    const int WB = 128 * LDB * 2;

#define EPILOGUE(MODE, BO, DH, DL, NXT_H, NXT_L, NXT_B) do {                        \
    __syncthreads();                                                                \
    if (NXT_B) cpW<512>(WhU, WlU, (const char*)(NXT_H), (const char*)(NXT_L), NXT_B, tid); \
    CP_COMMIT();                                                                    \
    for (int j = 0; j < 4; j++) {                                                   \
        wmma::store_matrix_sync(Fw, acc[j], 16, wmma::mem_row_major);               \
        __syncwarp();                                                               \
        int col = (jbase + j) * 16 + cb;                                            \
        float d[8];                                                                 \
        _Pragma("unroll") for (int u = 0; u < 8; u++) d[u] = Fw[rl * 16 + cb + u];  \
        float v[8];                                                                 \
        if (MODE == 0) {                                                            \
            float4 x0 = *(const float4*)&g_xji[(size_t)grow * 128 + col];           \
            float4 x1v = *(const float4*)&g_xji[(size_t)grow * 128 + col + 4];      \
            float xj[8] = {x0.x, x0.y, x0.z, x0.w, x1v.x, x1v.y, x1v.z, x1v.w};     \
            _Pragma("unroll") for (int u = 0; u < 8; u++) v[u] = xj[u] + silu_(d[u]); \
        } else if (MODE == 1) {                                                     \
            _Pragma("unroll") for (int u = 0; u < 8; u++) v[u] = silu_(d[u] + bsm[(BO) + col + u]); \
        } else if (MODE == 2) {                                                     \
            _Pragma("unroll") for (int u = 0; u < 8; u += 2) {                      \
                float2 o = ldPairE(Vh, Vl, row * LDB + col + u);                    \
                v[u]     = o.x + silu_(d[u] + bsm[(BO) + col + u]);                 \
                v[u + 1] = o.y + silu_(d[u + 1] + bsm[(BO) + col + u + 1]);         \
            }                                                                       \
        } else {                                                                    \
            bool ok = grow < E;                                                     \
            float xr[8] = {0, 0, 0, 0, 0, 0, 0, 0};                                 \
            if (ok) {                                                               \
                float4 x0 = *(const float4*)&x1[(size_t)grow * 128 + col];          \
                float4 x1v = *(const float4*)&x1[(size_t)grow * 128 + col + 4];     \
                xr[0] = x0.x; xr[1] = x0.y; xr[2] = x0.z; xr[3] = x0.w;             \
                xr[4] = x1v.x; xr[5] = x1v.y; xr[6] = x1v.z; xr[7] = x1v.w;         \
            }                                                                       \
            _Pragma("unroll") for (int u = 0; u < 8; u++) v[u] = silu_(d[u] + bsm[(BO) + col + u]) + xr[u]; \
        }                                                                           \
        _Pragma("unroll") for (int u = 0; u < 8; u += 2)                            \
            stsPairE(DH, DL, row * LDB + col + u, v[u], v[u + 1]);                  \
        __syncwarp();                                                               \
    }                                                                               \
    CP_WAIT0();                                                                     \
    __syncthreads();                                                                \
} while (0)

    mma_stripJ<4>(strip, jbase, 4, Th, Tl, Wh, Wl, acc);
    EPILOGUE(0, 0, Vh, Vl, g_Wph, g_Wpl, WB);
    mma_stripJ<4>(strip, jbase, 8, Vh, Vl, Wh, Wl, acc);
    EPILOGUE(1, 0, Th, Tl, g_Wph + 128 * LDB, g_Wpl + 128 * LDB, WB);
    mma_stripJ<4>(strip, jbase, 8, Th, Tl, Wh, Wl, acc);
    EPILOGUE(2, 128, Vh, Vl, g_Wph + 2 * 128 * LDB, g_Wpl + 2 * 128 * LDB, WB);
    mma_stripJ<4>(strip, jbase, 8, Vh, Vl, Wh, Wl, acc);
    EPILOGUE(3, 256, Vh, Vl, g_Wph + 3 * 128 * LDB, g_Wpl + 3 * 128 * LDB, WB);
    mma_stripJ<4>(strip, jbase, 8, Vh, Vl, Wh, Wl, acc);
    EPILOGUE(1, 384, Th, Tl, g_Wph + 4 * 128 * LDB, g_Wpl + 4 * 128 * LDB, WB);
    mma_stripJ<4>(strip, jbase, 8, Th, Tl, Wh, Wl, acc);
    EPILOGUE(2, 512, Vh, Vl, g_Wph + 5 * 128 * LDB, g_Wpl + 5 * 128 * LDB, WB);
    mma_stripJ<4>(strip, jbase, 8, Vh, Vl, Wh, Wl, acc);
    EPILOGUE(1, 640, Th, Tl, g_Wph + 6 * 128 * LDB, g_Wpl + 6 * 128 * LDB, WB);
    mma_stripJ<4>(strip, jbase, 8, Th, Tl, Wh, Wl, acc);
    EPILOGUE(2, 768, Vh, Vl, (const __nv_bfloat16*)0, (const __nv_bfloat16*)0, 0);

    for (int i = tid; i < 768; i += 512) F[i] = Wr_g[i];
    for (int i = tid; i < 768; i += 512) {
        int r = i / 6, q = i - 6 * r;
        int rw = tile0 + r;
        F[768 + i] = (rw < E) ? rbf0[(size_t)rw * 6 + q] : 0.f;
    }
    __syncthreads();

    for (int i = tid; i < 128 * 32; i += 512) {
        int rr = i >> 5, cbl = (i & 31) * 4;
        int gr = tile0 + rr;
        if (gr >= E) continue;
        float2 p0 = ldPairE(Vh, Vl, rr * LDB + cbl);
        float2 p1 = ldPairE(Vh, Vl, rr * LDB + cbl + 2);
        float rv[6];
#pragma unroll
        for (int q = 0; q < 6; q++) rv[q] = F[768 + rr * 6 + q];
        float e1v[4] = {p0.x, p0.y, p1.x, p1.y};
        float e2v[4];
#pragma unroll
        for (int u = 0; u < 4; u++) {
            float f = 0.f;
#pragma unroll
            for (int q = 0; q < 6; q++) f += rv[q] * F[q * 128 + cbl + u];
            e2v[u] = f * e1v[u];
        }
        *(float4*)&out[(size_t)gr * 128 + cbl] = make_float4(e1v[0], e1v[1], e1v[2], e1v[3]);
        *(float4*)&out[((size_t)E + gr) * 128 + cbl] = make_float4(e2v[0], e2v[1], e2v[2], e2v[3]);
    }
}

extern "C" void kernel_launch(void* const* d_in, const int* in_sizes, int n_in,
                              void* d_out, int out_size) {
    const float* x1    = (const float*)d_in[0];
    const float* rbf0  = (const float*)d_in[1];
    const float* sbf   = (const float*)d_in[2];
    const float* tb    = (const float*)d_in[3];
    const int* idx_kj  = (const int*)d_in[4];
    const int* idx_ji  = (const int*)d_in[5];
    const float* W_rbf1 = (const float*)d_in[6];
    const float* W_rbf2 = (const float*)d_in[7];
    const float* W_sbf1 = (const float*)d_in[8];
    const float* W_sbf2 = (const float*)d_in[9];
    const float* W_t1   = (const float*)d_in[10];
    const float* W_t2   = (const float*)d_in[11];
    const float* W_rbf  = (const float*)d_in[12];
    const float* W_kj   = (const float*)d_in[13];
    const float* b_kj   = (const float*)d_in[14];
    const float* W_ji   = (const float*)d_in[15];
    const float* b_ji   = (const float*)d_in[16];
    const float* W_down = (const float*)d_in[17];
    const float* W_up   = (const float*)d_in[18];
    const float* rbW1   = (const float*)d_in[19];
    const float* rbb1   = (const float*)d_in[20];
    const float* rbW2   = (const float*)d_in[21];
    const float* rbb2   = (const float*)d_in[22];
    const float* W_lin  = (const float*)d_in[23];
    const float* b_lin  = (const float*)d_in[24];
    const float* raW1   = (const float*)d_in[25];
    const float* rab1   = (const float*)d_in[26];
    const float* raW2   = (const float*)d_in[27];
    const float* rab2   = (const float*)d_in[28];
    float* out = (float*)d_out;

    const int E = in_sizes[0] / 128;
    const int T = in_sizes[4];
    const int etiles = (E + 127) / 128;
    const int nchunks = (T + 31) / 32;
    const int nprep = 10 * 128 * LDB + 64 * LDB;
    const int nprep2 = 304 * 16 + 48 * 16;

    cudaFuncSetAttribute(k_pre_wmma,  cudaFuncAttributeMaxDynamicSharedMemorySize, SM_PRE);
    cudaFuncSetAttribute(k_triplet,   cudaFuncAttributeMaxDynamicSharedMemorySize, SM_TRI);
    cudaFuncSetAttribute(k_post_wmma, cudaFuncAttributeMaxDynamicSharedMemorySize, SM_POST);

    k_wcomb<<<3, 256>>>(W_rbf1, W_rbf2);
    k_wprep<<<(nprep + 255) / 256, 256>>>(rbW1, rbW2, W_lin, raW1, raW2, W_up, W_ji, W_kj, W_down);
    k_wprep2<<<(nprep2 + 255) / 256, 256>>>(W_t1, W_sbf1);
    k_pre_wmma<<<etiles, 512, SM_PRE>>>(x1, rbf0, b_ji, b_kj, E);
    k_triplet<<<296, 256, SM_TRI>>>(sbf, tb, idx_kj, idx_ji, W_sbf2, W_t2, T, nchunks);
    k_post_wmma<<<etiles, 512, SM_POST>>>(x1, rbf0, W_rbf, rbb1, rbb2, b_lin, rab1, rab2, out, E);
}

// round 17
// speedup vs baseline: 1.3428x; 1.1608x over previous
#include <cuda_runtime.h>
#include <cuda_bf16.h>
#include <mma.h>
#include <cstdint>

using namespace nvcuda;

#define LDB 136
#define EPAD 100096  // 782*128

__device__ float g_xji [(size_t)EPAD * 128];
__device__ float g_xkjd[(size_t)EPAD * 64];
__device__ float g_agg [(size_t)EPAD * 64];
__device__ float g_Wrbfc[768];
// 0 rbW1, 1 rbW2, 2 Wlin, 3 raW1a, 4 raW2a, 5 raW1b, 6 raW2b, 7 Wji, 8 Wkj, 9 Wdown(n<64)
__device__ __align__(16) __nv_bfloat16 g_Wph[10 * 128 * LDB];
__device__ __align__(16) __nv_bfloat16 g_Wpl[10 * 128 * LDB];
__device__ __align__(16) __nv_bfloat16 g_Wuph[64 * LDB];
__device__ __align__(16) __nv_bfloat16 g_Wupl[64 * LDB];
__device__ __align__(16) __nv_bfloat16 g_Wt1h[304 * 16];
__device__ __align__(16) __nv_bfloat16 g_Wt1l[304 * 16];
__device__ __align__(16) __nv_bfloat16 g_Ws1h[48 * 16];
__device__ __align__(16) __nv_bfloat16 g_Ws1l[48 * 16];

extern __shared__ char smraw[];

typedef unsigned long long u64;

__device__ __forceinline__ float silu_(float x) { return x / (1.0f + __expf(-x)); }
__device__ __forceinline__ u64 pack2(float lo, float hi) {
    u64 d; asm("mov.b64 %0,{%1,%2};" : "=l"(d) : "r"(__float_as_uint(lo)), "r"(__float_as_uint(hi)));
    return d;
}
__device__ __forceinline__ void ffma2(u64& d, u64 a, u64 b) {
    asm("fma.rn.f32x2 %0,%1,%2,%0;" : "+l"(d) : "l"(a), "l"(b));
}
__device__ __forceinline__ float2 unpack2(u64 v) {
    unsigned lo, hi; asm("mov.b64 {%0,%1},%2;" : "=r"(lo), "=r"(hi) : "l"(v));
    return make_float2(__uint_as_float(lo), __uint_as_float(hi));
}
__device__ __forceinline__ uint32_t smem_to_u32(const void* p) {
    uint32_t a;
    asm("{ .reg .u64 t; cvta.to.shared.u64 t, %1; cvt.u32.u64 %0, t; }" : "=r"(a) : "l"(p));
    return a;
}
__device__ __forceinline__ void stsPairE(__nv_bfloat16* H, __nv_bfloat16* L, int eoff, float v0, float v1) {
    __nv_bfloat162 hp, lp;
    hp.x = __float2bfloat16(v0); hp.y = __float2bfloat16(v1);
    lp.x = __float2bfloat16(v0 - __bfloat162float(hp.x));
    lp.y = __float2bfloat16(v1 - __bfloat162float(hp.y));
    *(__nv_bfloat162*)(H + eoff) = hp;
    *(__nv_bfloat162*)(L + eoff) = lp;
}
__device__ __forceinline__ float2 ldPairE(const __nv_bfloat16* H, const __nv_bfloat16* L, int eoff) {
    __nv_bfloat162 h = *(const __nv_bfloat162*)(H + eoff);
    __nv_bfloat162 l = *(const __nv_bfloat162*)(L + eoff);
    return make_float2(__bfloat162float(h.x) + __bfloat162float(l.x),
                       __bfloat162float(h.y) + __bfloat162float(l.y));
}
__device__ __forceinline__ void redg4(float* dst, float a, float b, float c, float d) {
    asm volatile("red.global.add.v4.f32 [%0], {%1, %2, %3, %4};"
                 :: "l"(dst), "f"(a), "f"(b), "f"(c), "f"(d) : "memory");
}
template <int NT>
__device__ __forceinline__ void cpW(uint32_t whU, uint32_t wlU,
                                    const char* sh, const char* sl, int bytes, int tid) {
    for (int i = tid * 16; i < bytes; i += NT * 16) {
        asm volatile("cp.async.cg.shared.global [%0],[%1],16;" :: "r"(whU + i), "l"(sh + i) : "memory");
        asm volatile("cp.async.cg.shared.global [%0],[%1],16;" :: "r"(wlU + i), "l"(sl + i) : "memory");
    }
}
#define CP_COMMIT() asm volatile("cp.async.commit_group;" ::: "memory")
#define CP_WAIT0()  asm volatile("cp.async.wait_group 0;" ::: "memory")

// raw mma.sync helpers (documented fragment layouts)
__device__ __forceinline__ void ldsm4(uint32_t p, uint32_t& r0, uint32_t& r1, uint32_t& r2, uint32_t& r3) {
    asm volatile("ldmatrix.sync.aligned.m8n8.x4.shared.b16 {%0,%1,%2,%3}, [%4];"
                 : "=r"(r0), "=r"(r1), "=r"(r2), "=r"(r3) : "r"(p));
}
__device__ __forceinline__ void ldsm4t(uint32_t p, uint32_t& r0, uint32_t& r1, uint32_t& r2, uint32_t& r3) {
    asm volatile("ldmatrix.sync.aligned.m8n8.x4.trans.shared.b16 {%0,%1,%2,%3}, [%4];"
                 : "=r"(r0), "=r"(r1), "=r"(r2), "=r"(r3) : "r"(p));
}
__device__ __forceinline__ void mma_bf16(float* d, uint32_t a0, uint32_t a1, uint32_t a2, uint32_t a3,
                                         uint32_t b0, uint32_t b1) {
    asm volatile("mma.sync.aligned.m16n8k16.row.col.f32.bf16.bf16.f32 "
                 "{%0,%1,%2,%3}, {%4,%5,%6,%7}, {%8,%9}, {%0,%1,%2,%3};"
                 : "+f"(d[0]), "+f"(d[1]), "+f"(d[2]), "+f"(d[3])
                 : "r"(a0), "r"(a1), "r"(a2), "r"(a3), "r"(b0), "r"(b1));
}

// ---------------- K0a ----------------
__global__ void k_wcomb(const float* __restrict__ W1, const float* __restrict__ W2) {
    int i = blockIdx.x * blockDim.x + threadIdx.x;
    if (i < 768) {
        int r = i >> 7, c = i & 127;
        float s = 0.f;
#pragma unroll
        for (int b = 0; b < 8; b++) s += W1[r * 8 + b] * W2[b * 128 + c];
        g_Wrbfc[i] = s;
    }
}

// ---------------- K0b ----------------
__global__ void k_wprep(const float* __restrict__ rbW1, const float* __restrict__ rbW2,
                        const float* __restrict__ Wlin, const float* __restrict__ raW1,
                        const float* __restrict__ raW2, const float* __restrict__ Wup,
                        const float* __restrict__ Wji, const float* __restrict__ Wkj,
                        const float* __restrict__ Wdown) {
    int i = blockIdx.x * blockDim.x + threadIdx.x;
    const int PER = 128 * LDB;
    if (i < 10 * PER) {
        int s = i / PER, e = i - s * PER;
        int k = e / LDB, n = e - k * LDB;
        float v = 0.f;
        if (s == 9) { if (n < 64) v = Wdown[k * 64 + n]; }
        else if (n < 128) {
            const float* W = (s == 0) ? rbW1 : (s == 1) ? rbW2 : (s == 2) ? Wlin :
                             (s == 3) ? raW1 : (s == 4) ? raW2 : (s == 5) ? raW1 + 16384 :
                             (s == 6) ? raW2 + 16384 : (s == 7) ? Wji : Wkj;
            v = W[k * 128 + n];
        }
        __nv_bfloat16 h = __float2bfloat16(v);
        g_Wph[i] = h;
        g_Wpl[i] = __float2bfloat16(v - __bfloat162float(h));
    } else if (i < 10 * PER + 64 * LDB) {
        int e = i - 10 * PER;
        int k = e / LDB, n = e - k * LDB;
        float v = (n < 128) ? Wup[k * 128 + n] : 0.f;
        __nv_bfloat16 h = __float2bfloat16(v);
        g_Wuph[e] = h;
        g_Wupl[e] = __float2bfloat16(v - __bfloat162float(h));
    }
}

// ---------------- K0c ----------------
__global__ void k_wprep2(const float* __restrict__ Wt1, const float* __restrict__ Ws1) {
    int i = blockIdx.x * blockDim.x + threadIdx.x;
    if (i < 304 * 16) {
        int k = i >> 4, n = i & 15;
        float v = (k < 294 && n < 8) ? Wt1[k * 8 + n] : 0.f;
        __nv_bfloat16 h = __float2bfloat16(v);
        g_Wt1h[i] = h;
        g_Wt1l[i] = __float2bfloat16(v - __bfloat162float(h));
    } else if (i < 304 * 16 + 48 * 16) {
        int e = i - 304 * 16;
        int k = e >> 4, n = e & 15;
        float v = (k < 42 && n < 8) ? Ws1[k * 8 + n] : 0.f;
        __nv_bfloat16 h = __float2bfloat16(v);
        g_Ws1h[e] = h;
        g_Ws1l[e] = __float2bfloat16(v - __bfloat162float(h));
    }
}

// ============ smem layout (512 threads, 16 warps) ============
#define OFF_VH 0
#define OFF_VL 34816
#define OFF_TH 69632
#define OFF_TL 104448
#define OFF_WH 139264
#define OFF_WL 174080
#define OFF_F  208896
#define OFF_BS 225280
#define SM_POST (225280 + 3584)
#define SM_PRE  (225280 + 4096)

typedef wmma::fragment<wmma::accumulator, 16, 16, 16, float> AccFrag;

template <int JM>
__device__ __forceinline__ void mma_stripJ(int strip, int jbase, int ksteps,
        const __nv_bfloat16* Ah, const __nv_bfloat16* Al,
        const __nv_bfloat16* Wh, const __nv_bfloat16* Wl,
        AccFrag (&acc)[JM]) {
#pragma unroll
    for (int j = 0; j < JM; j++) wmma::fill_fragment(acc[j], 0.f);
    for (int kk = 0; kk < ksteps; kk++) {
        wmma::fragment<wmma::matrix_a, 16, 16, 16, __nv_bfloat16, wmma::row_major> ah, al;
        wmma::load_matrix_sync(ah, Ah + strip * 16 * LDB + kk * 16, LDB);
        wmma::load_matrix_sync(al, Al + strip * 16 * LDB + kk * 16, LDB);
#pragma unroll
        for (int j = 0; j < JM; j++) {
            wmma::fragment<wmma::matrix_b, 16, 16, 16, __nv_bfloat16, wmma::row_major> bh, bl;
            wmma::load_matrix_sync(bh, Wh + kk * 16 * LDB + (jbase + j) * 16, LDB);
            wmma::load_matrix_sync(bl, Wl + kk * 16 * LDB + (jbase + j) * 16, LDB);
            wmma::mma_sync(acc[j], ah, bh, acc[j]);
            wmma::mma_sync(acc[j], ah, bl, acc[j]);
            wmma::mma_sync(acc[j], al, bh, acc[j]);
        }
    }
}

// raw-mma stage for k_post: 8 n8-block accumulators per warp
__device__ __forceinline__ void mma_stage_r(int strip, int h, int lane, int ksteps,
        uint32_t AhU, uint32_t AlU, uint32_t WhU, uint32_t WlU, float (&acc)[8][4]) {
#pragma unroll
    for (int b = 0; b < 8; b++)
#pragma unroll
        for (int q = 0; q < 4; q++) acc[b][q] = 0.f;
    const uint32_t la = ((strip * 16 + (lane & 15)) * LDB + (lane >> 4) * 8) * 2;
    for (int kk = 0; kk < ksteps; kk++) {
        uint32_t ah0, ah1, ah2, ah3, al0, al1, al2, al3;
        ldsm4(AhU + la + kk * 32, ah0, ah1, ah2, ah3);
        ldsm4(AlU + la + kk * 32, al0, al1, al2, al3);
#pragma unroll
        for (int j = 0; j < 4; j++) {
            uint32_t off = ((kk * 16 + (lane & 15)) * LDB + (h * 4 + j) * 16 + (lane >> 4) * 8) * 2;
            uint32_t bh0, bh1, bh2, bh3, bl0, bl1, bl2, bl3;
            ldsm4t(WhU + off, bh0, bh1, bh2, bh3);
            ldsm4t(WlU + off, bl0, bl1, bl2, bl3);
            mma_bf16(acc[2 * j],     ah0, ah1, ah2, ah3, bh0, bh1);
            mma_bf16(acc[2 * j],     ah0, ah1, ah2, ah3, bl0, bl1);
            mma_bf16(acc[2 * j],     al0, al1, al2, al3, bh0, bh1);
            mma_bf16(acc[2 * j + 1], ah0, ah1, ah2, ah3, bh2, bh3);
            mma_bf16(acc[2 * j + 1], ah0, ah1, ah2, ah3, bl2, bl3);
            mma_bf16(acc[2 * j + 1], al0, al1, al2, al3, bh2, bh3);
        }
    }
}

// ---------------- K1: wmma edge preprocess (512 threads, unchanged) ----------------
__global__ void __launch_bounds__(512, 1)
k_pre_wmma(const float* __restrict__ x1, const float* __restrict__ rbf0,
           const float* __restrict__ bji, const float* __restrict__ bkj, int E) {
    char* sm = smraw;
    __nv_bfloat16* Vh = (__nv_bfloat16*)(sm + OFF_VH);
    __nv_bfloat16* Vl = (__nv_bfloat16*)(sm + OFF_VL);
    __nv_bfloat16* Th = (__nv_bfloat16*)(sm + OFF_TH);
    __nv_bfloat16* Tl = (__nv_bfloat16*)(sm + OFF_TL);
    __nv_bfloat16* Wh = (__nv_bfloat16*)(sm + OFF_WH);
    __nv_bfloat16* Wl = (__nv_bfloat16*)(sm + OFF_WL);
    float* F   = (float*)(sm + OFF_F);
    float* bsm = (float*)(sm + OFF_BS);
    const uint32_t WhU = smem_to_u32(Wh), WlU = smem_to_u32(Wl);
    const int tid = threadIdx.x;
    const int w = tid >> 5, lane = tid & 31;
    const int strip = w >> 1, h = w & 1, jbase = h * 4;
    const int rl = lane >> 1, row = strip * 16 + rl, cb = (lane & 1) * 8;
    const int tile0 = blockIdx.x * 128;
    const int grow = tile0 + row;
    float* Fw = F + w * 256;
    const int WB = 128 * LDB * 2;

    cpW<512>(WhU, WlU, (const char*)(g_Wph + 7 * 128 * LDB), (const char*)(g_Wpl + 7 * 128 * LDB), WB, tid);
    CP_COMMIT();

    if (tid < 128) { bsm[tid] = bji[tid]; bsm[128 + tid] = bkj[tid]; }
    for (int i = tid; i < 768; i += 512) bsm[256 + i] = g_Wrbfc[i];
    {
        float4 z = make_float4(0.f, 0.f, 0.f, 0.f);
        for (int i = tid; i < 128 * 16; i += 512) {
            int r = i >> 4, c4 = (i & 15) * 4;
            *(float4*)&g_agg[(size_t)(tile0 + r) * 64 + c4] = z;
        }
    }
    {
        int r = tid >> 2, cq = (tid & 3) * 32;
        int rw = tile0 + r;
        if (rw < E) {
            const float4* xr = (const float4*)&x1[(size_t)rw * 128 + cq];
#pragma unroll
            for (int u = 0; u < 8; u++) {
                float4 v = xr[u];
                int c = cq + u * 4;
                stsPairE(Th, Tl, r * LDB + c, v.x, v.y);
                stsPairE(Th, Tl, r * LDB + c + 2, v.z, v.w);
            }
        } else {
            for (int u = 0; u < 16; u++) stsPairE(Th, Tl, r * LDB + cq + u * 2, 0.f, 0.f);
        }
    }
    float rv[6];
#pragma unroll
    for (int q = 0; q < 6; q++) rv[q] = (grow < E) ? rbf0[(size_t)grow * 6 + q] : 0.f;
    CP_WAIT0();
    __syncthreads();

    AccFrag acc[4];

    mma_stripJ<4>(strip, jbase, 8, Th, Tl, Wh, Wl, acc);
    __syncthreads();
    cpW<512>(WhU, WlU, (const char*)(g_Wph + 8 * 128 * LDB), (const char*)(g_Wpl + 8 * 128 * LDB), WB, tid);
    CP_COMMIT();
    for (int j = 0; j < 4; j++) {
        wmma::store_matrix_sync(Fw, acc[j], 16, wmma::mem_row_major);
        __syncwarp();
        int col = (jbase + j) * 16 + cb;
        float v[8];
#pragma unroll
        for (int u = 0; u < 8; u++) v[u] = silu_(Fw[rl * 16 + cb + u] + bsm[col + u]);
        *(float4*)&g_xji[(size_t)grow * 128 + col]     = make_float4(v[0], v[1], v[2], v[3]);
        *(float4*)&g_xji[(size_t)grow * 128 + col + 4] = make_float4(v[4], v[5], v[6], v[7]);
        __syncwarp();
    }
    CP_WAIT0();
    __syncthreads();

    mma_stripJ<4>(strip, jbase, 8, Th, Tl, Wh, Wl, acc);
    __syncthreads();
    cpW<512>(WhU, WlU, (const char*)(g_Wph + 9 * 128 * LDB), (const char*)(g_Wpl + 9 * 128 * LDB), WB, tid);
    CP_COMMIT();
    for (int j = 0; j < 4; j++) {
        wmma::store_matrix_sync(Fw, acc[j], 16, wmma::mem_row_major);
        __syncwarp();
        int col = (jbase + j) * 16 + cb;
        float v[8];
#pragma unroll
        for (int u = 0; u < 8; u++) {
            float f = 0.f;
#pragma unroll
            for (int q = 0; q < 6; q++) f += rv[q] * bsm[256 + q * 128 + col + u];
            v[u] = silu_(Fw[rl * 16 + cb + u] + bsm[128 + col + u]) * f;
        }
#pragma unroll
        for (int u = 0; u < 8; u += 2) stsPairE(Vh, Vl, row * LDB + col + u, v[u], v[u + 1]);
        __syncwarp();
    }
    CP_WAIT0();
    __syncthreads();

    AccFrag ac2[2];
    mma_stripJ<2>(strip, h * 2, 8, Vh, Vl, Wh, Wl, ac2);
    for (int j = 0; j < 2; j++) {
        wmma::store_matrix_sync(Fw, ac2[j], 16, wmma::mem_row_major);
        __syncwarp();
        int col = (h * 2 + j) * 16 + cb;
        float v[8];
#pragma unroll
        for (int u = 0; u < 8; u++) v[u] = silu_(Fw[rl * 16 + cb + u]);
        *(float4*)&g_xkjd[(size_t)grow * 64 + col]     = make_float4(v[0], v[1], v[2], v[3]);
        *(float4*)&g_xkjd[(size_t)grow * 64 + col + 4] = make_float4(v[4], v[5], v[6], v[7]);
        __syncwarp();
    }
}

// ---------------- K2: persistent triplet (unchanged from R15 winner) ----------------
#define SM_TRI 83200

__device__ __forceinline__ void tri_ld(const float* __restrict__ tb, const float* __restrict__ sbf,
                                       const int* __restrict__ idx_kj, const int* __restrict__ idx_ji,
                                       int t0, int T, int tid,
                                       float4 (&tbuf)[10], float4 (&sbuf)[2], int& ikr, int& ijr) {
    int nrows = T - t0; if (nrows > 32) nrows = 32;
    const float* src = tb + (size_t)t0 * 294;
    int lim = nrows * 294;
#pragma unroll
    for (int k = 0; k < 10; k++) {
        int i4 = tid + k * 256;
        float4 v = make_float4(0.f, 0.f, 0.f, 0.f);
        if (i4 < 2352) {
            int e = i4 * 4;
            if (e + 4 <= lim) v = *(const float4*)(src + e);
            else { float t[4] = {0, 0, 0, 0}; for (int j = 0; j < 4; j++) if (e + j < lim) t[j] = src[e + j]; v = make_float4(t[0], t[1], t[2], t[3]); }
        }
        tbuf[k] = v;
    }
    const float* ss = sbf + (size_t)t0 * 42;
    int lim2 = nrows * 42;
#pragma unroll
    for (int k = 0; k < 2; k++) {
        int i4 = tid + k * 256;
        float4 v = make_float4(0.f, 0.f, 0.f, 0.f);
        if (i4 < 336) {
            int e = i4 * 4;
            if (e + 4 <= lim2) v = *(const float4*)(ss + e);
            else { float t[4] = {0, 0, 0, 0}; for (int j = 0; j < 4; j++) if (e + j < lim2) t[j] = ss[e + j]; v = make_float4(t[0], t[1], t[2], t[3]); }
        }
        sbuf[k] = v;
    }
    if (tid < 32) {
        int t = t0 + tid;
        ikr = (t < T) ? idx_kj[t] : 0;
        ijr = (t < T) ? idx_ji[t] : 0;
    }
}

__global__ void __launch_bounds__(256, 2)
k_triplet(const float* __restrict__ sbf, const float* __restrict__ tb,
          const int* __restrict__ idx_kj, const int* __restrict__ idx_ji,
          const float* __restrict__ Ws2, const float* __restrict__ Wt2,
          int T, int nchunks) {
    char* sm = smraw;
    __nv_bfloat16* TH = (__nv_bfloat16*)(sm);
    __nv_bfloat16* TL = (__nv_bfloat16*)(sm + 19456);
    __nv_bfloat16* SH = (__nv_bfloat16*)(sm + 38912);
    __nv_bfloat16* SL = (__nv_bfloat16*)(sm + 41984);
    __nv_bfloat16* W1H = (__nv_bfloat16*)(sm + 45056);
    __nv_bfloat16* W1L = (__nv_bfloat16*)(sm + 54784);
    __nv_bfloat16* S1H = (__nv_bfloat16*)(sm + 64512);
    __nv_bfloat16* S1L = (__nv_bfloat16*)(sm + 66048);
    float* WT2 = (float*)(sm + 67584);
    float* WS2 = (float*)(sm + 69632);
    float* FT0 = (float*)(sm + 71680);
    float* FT1 = (float*)(sm + 73984);
    float* FT2 = (float*)(sm + 76288);
    float* FS  = (float*)(sm + 78592);
    float* TMT = (float*)(sm + 80896);
    float* TMS = (float*)(sm + 81920);
    int* IK = (int*)(sm + 82944);
    int* IJ = (int*)(sm + 83072);
    const int tid = threadIdx.x;
    const int w = tid >> 5;
    const int m = w & 1, kg = w >> 1;

    for (int i = tid; i < 11264; i += 256) ((uint32_t*)sm)[i] = 0;
    for (int i = tid; i < 2432; i += 256) {
        ((uint32_t*)W1H)[i] = ((const uint32_t*)g_Wt1h)[i];
        ((uint32_t*)W1L)[i] = ((const uint32_t*)g_Wt1l)[i];
    }
    for (int i = tid; i < 384; i += 256) {
        ((uint32_t*)S1H)[i] = ((const uint32_t*)g_Ws1h)[i];
        ((uint32_t*)S1L)[i] = ((const uint32_t*)g_Ws1l)[i];
    }
    for (int i = tid; i < 512; i += 256) { WT2[i] = Wt2[i]; WS2[i] = Ws2[i]; }

    float4 tbuf[10]; float4 sbuf[2]; int ikr = 0, ijr = 0;
    int ch = blockIdx.x;
    if (ch < nchunks) tri_ld(tb, sbf, idx_kj, idx_ji, ch * 32, T, tid, tbuf, sbuf, ikr, ijr);
    __syncthreads();

    for (; ch < nchunks; ch += gridDim.x) {
        const int t0 = ch * 32;
#pragma unroll
        for (int k = 0; k < 10; k++) {
            int i4 = tid + k * 256;
            if (i4 < 2352) {
                int e = i4 * 4;
                float vv[4] = {tbuf[k].x, tbuf[k].y, tbuf[k].z, tbuf[k].w};
#pragma unroll
                for (int j = 0; j < 4; j++) {
                    int ee = e + j; int r = ee / 294, c = ee - 294 * r;
                    __nv_bfloat16 hh = __float2bfloat16(vv[j]);
                    TH[r * 304 + c] = hh;
                    TL[r * 304 + c] = __float2bfloat16(vv[j] - __bfloat162float(hh));
                }
            }
        }
#pragma unroll
        for (int k = 0; k < 2; k++) {
            int i4 = tid + k * 256;
            if (i4 < 336) {
                int e = i4 * 4;
                float vv[4] = {sbuf[k].x, sbuf[k].y, sbuf[k].z, sbuf[k].w};
#pragma unroll
                for (int j = 0; j < 4; j++) {
                    int ee = e + j; int r = ee / 42, c = ee - 42 * r;
                    __nv_bfloat16 hh = __float2bfloat16(vv[j]);
                    SH[r * 48 + c] = hh;
                    SL[r * 48 + c] = __float2bfloat16(vv[j] - __bfloat162float(hh));
                }
            }
        }
        if (tid < 32) { IK[tid] = ikr; IJ[tid] = ijr; }
        __syncthreads();
        int chn = ch + gridDim.x;
        if (chn < nchunks) tri_ld(tb, sbf, idx_kj, idx_ji, chn * 32, T, tid, tbuf, sbuf, ikr, ijr);
        {
            wmma::fragment<wmma::accumulator, 16, 16, 16, float> acc;
            wmma::fill_fragment(acc, 0.f);
            const __nv_bfloat16 *Ah, *Al, *Bh, *Bl; int lda, k0, nk; float* Fo;
            if (kg == 3) { Ah = SH + m * 16 * 48; Al = SL + m * 16 * 48; Bh = S1H; Bl = S1L; lda = 48; k0 = 0; nk = 3; Fo = FS; }
            else {
                Ah = TH + m * 16 * 304; Al = TL + m * 16 * 304; Bh = W1H; Bl = W1L; lda = 304;
                k0 = (kg == 0) ? 0 : (kg == 1) ? 7 : 13;
                nk = (kg == 0) ? 7 : 6;
                Fo = (kg == 0) ? FT0 : (kg == 1) ? FT1 : FT2;
            }
            for (int kk = k0; kk < k0 + nk; kk++) {
                wmma::fragment<wmma::matrix_a, 16, 16, 16, __nv_bfloat16, wmma::row_major> ah, al;
                wmma::fragment<wmma::matrix_b, 16, 16, 16, __nv_bfloat16, wmma::row_major> bh, bl;
                wmma::load_matrix_sync(ah, Ah + kk * 16, lda);
                wmma::load_matrix_sync(al, Al + kk * 16, lda);
                wmma::load_matrix_sync(bh, Bh + kk * 256, 16);
                wmma::load_matrix_sync(bl, Bl + kk * 256, 16);
                wmma::mma_sync(acc, ah, bh, acc);
                wmma::mma_sync(acc, ah, bl, acc);
                wmma::mma_sync(acc, al, bh, acc);
            }
            wmma::store_matrix_sync(Fo + m * 16 * 18, acc, 18, wmma::mem_row_major);
        }
        __syncthreads();
        {
            int r = tid >> 3, c = tid & 7;
            TMT[tid] = FT0[r * 18 + c] + FT1[r * 18 + c] + FT2[r * 18 + c];
            TMS[tid] = FS[r * 18 + c];
        }
        __syncthreads();
        {
            const int tr = tid >> 3, c8 = (tid & 7) * 8;
            if (t0 + tr < T) {
                u64 tp[4] = {0, 0, 0, 0}, sp[4] = {0, 0, 0, 0};
#pragma unroll
                for (int r = 0; r < 8; r++) {
                    float at = TMT[tr * 8 + r], bs = TMS[tr * 8 + r];
                    u64 a = pack2(at, at), b = pack2(bs, bs);
                    const ulonglong2* w2 = (const ulonglong2*)(WT2 + r * 64 + c8);
                    const ulonglong2* v2 = (const ulonglong2*)(WS2 + r * 64 + c8);
                    ulonglong2 wA = w2[0], wB = w2[1], vA = v2[0], vB = v2[1];
                    ffma2(tp[0], a, wA.x); ffma2(tp[1], a, wA.y); ffma2(tp[2], a, wB.x); ffma2(tp[3], a, wB.y);
                    ffma2(sp[0], b, vA.x); ffma2(sp[1], b, vA.y); ffma2(sp[2], b, vB.x); ffma2(sp[3], b, vB.y);
                }
                size_t gk = (size_t)IK[tr] * 64 + c8;
                float4 g0 = *(const float4*)&g_xkjd[gk];
                float4 g1 = *(const float4*)&g_xkjd[gk + 4];
                float* dst = &g_agg[(size_t)IJ[tr] * 64 + c8];
                float2 t0v = unpack2(tp[0]), t1v = unpack2(tp[1]), t2v = unpack2(tp[2]), t3v = unpack2(tp[3]);
                float2 s0v = unpack2(sp[0]), s1v = unpack2(sp[1]), s2v = unpack2(sp[2]), s3v = unpack2(sp[3]);
                redg4(dst,     t0v.x * s0v.x * g0.x, t0v.y * s0v.y * g0.y,
                               t1v.x * s1v.x * g0.z, t1v.y * s1v.y * g0.w);
                redg4(dst + 4, t2v.x * s2v.x * g1.x, t2v.y * s2v.y * g1.y,
                               t3v.x * s3v.x * g1.z, t3v.y * s3v.y * g1.w);
            }
        }
        __syncthreads();
    }
}

// ---------------- K3: raw-mma bf16x3 edge epilogue chain (512 threads) ----------------
__global__ void __launch_bounds__(512, 1)
k_post_mma(const float* __restrict__ x1, const float* __restrict__ rbf0,
           const float* __restrict__ Wr_g,
           const float* __restrict__ rbb1, const float* __restrict__ rbb2,
           const float* __restrict__ blin,
           const float* __restrict__ rab1, const float* __restrict__ rab2,
           float* __restrict__ out, int E) {
    char* sm = smraw;
    __nv_bfloat16* Vh = (__nv_bfloat16*)(sm + OFF_VH);
    __nv_bfloat16* Vl = (__nv_bfloat16*)(sm + OFF_VL);
    __nv_bfloat16* Th = (__nv_bfloat16*)(sm + OFF_TH);
    __nv_bfloat16* Tl = (__nv_bfloat16*)(sm + OFF_TL);
    __nv_bfloat16* Wh = (__nv_bfloat16*)(sm + OFF_WH);
    __nv_bfloat16* Wl = (__nv_bfloat16*)(sm + OFF_WL);
    float* F   = (float*)(sm + OFF_F);
    float* bsm = (float*)(sm + OFF_BS);
    const uint32_t WhU = smem_to_u32(Wh), WlU = smem_to_u32(Wl);
    const uint32_t VhU = smem_to_u32(Vh), VlU = smem_to_u32(Vl);
    const uint32_t ThU = smem_to_u32(Th), TlU = smem_to_u32(Tl);
    const int tid = threadIdx.x;
    const int w = tid >> 5, lane = tid & 31;
    const int strip = w >> 1, h = w & 1;
    const int lr = lane >> 2, lc2 = (lane & 3) * 2;
    const int rowA = strip * 16 + lr, rowB = rowA + 8;
    const int tile0 = blockIdx.x * 128;

    if (tid < 128) {
        int i = tid;
        bsm[i] = rbb1[i]; bsm[128 + i] = rbb2[i]; bsm[256 + i] = blin[i];
        bsm[384 + i] = rab1[i]; bsm[512 + i] = rab2[i];
        bsm[640 + i] = rab1[128 + i]; bsm[768 + i] = rab2[128 + i];
    }
    {
        int r = tid >> 2, cq = (tid & 3) * 16;
        const float4* ag = (const float4*)&g_agg[(size_t)(tile0 + r) * 64 + cq];
#pragma unroll
        for (int u = 0; u < 4; u++) {
            float4 v = ag[u];
            int c = cq + u * 4;
            stsPairE(Th, Tl, r * LDB + c, v.x, v.y);
            stsPairE(Th, Tl, r * LDB + c + 2, v.z, v.w);
        }
    }
    cpW<512>(WhU, WlU, (const char*)g_Wuph, (const char*)g_Wupl, 64 * LDB * 2, tid);
    CP_COMMIT(); CP_WAIT0();
    __syncthreads();

    float acc[8][4];
    const int WB = 128 * LDB * 2;

#define EPI_R(MODE, BO, DH, DL, NXT_H, NXT_L, NXT_B) do {                             \
    __syncthreads();                                                                  \
    if (NXT_B) cpW<512>(WhU, WlU, (const char*)(NXT_H), (const char*)(NXT_L), NXT_B, tid); \
    CP_COMMIT();                                                                      \
    _Pragma("unroll")                                                                 \
    for (int b = 0; b < 8; b++) {                                                     \
        int col = (h * 4 + (b >> 1)) * 16 + (b & 1) * 8 + lc2;                        \
        float v0, v1, v2, v3;                                                         \
        if (MODE == 0) {                                                              \
            float2 xa = *(const float2*)&g_xji[(size_t)(tile0 + rowA) * 128 + col];   \
            float2 xb = *(const float2*)&g_xji[(size_t)(tile0 + rowB) * 128 + col];   \
            v0 = xa.x + silu_(acc[b][0]); v1 = xa.y + silu_(acc[b][1]);               \
            v2 = xb.x + silu_(acc[b][2]); v3 = xb.y + silu_(acc[b][3]);               \
        } else if (MODE == 1) {                                                       \
            float b0 = bsm[(BO) + col], b1 = bsm[(BO) + col + 1];                     \
            v0 = silu_(acc[b][0] + b0); v1 = silu_(acc[b][1] + b1);                   \
            v2 = silu_(acc[b][2] + b0); v3 = silu_(acc[b][3] + b1);                   \
        } else if (MODE == 2) {                                                       \
            float b0 = bsm[(BO) + col], b1 = bsm[(BO) + col + 1];                     \
            float2 oa = ldPairE(Vh, Vl, rowA * LDB + col);                            \
            float2 ob = ldPairE(Vh, Vl, rowB * LDB + col);                            \
            v0 = oa.x + silu_(acc[b][0] + b0); v1 = oa.y + silu_(acc[b][1] + b1);     \
            v2 = ob.x + silu_(acc[b][2] + b0); v3 = ob.y + silu_(acc[b][3] + b1);     \
        } else {                                                                      \
            float b0 = bsm[(BO) + col], b1 = bsm[(BO) + col + 1];                     \
            float2 xa = make_float2(0.f, 0.f), xb = make_float2(0.f, 0.f);            \
            if (tile0 + rowA < E) xa = *(const float2*)&x1[(size_t)(tile0 + rowA) * 128 + col]; \
            if (tile0 + rowB < E) xb = *(const float2*)&x1[(size_t)(tile0 + rowB) * 128 + col]; \
            v0 = silu_(acc[b][0] + b0) + xa.x; v1 = silu_(acc[b][1] + b1) + xa.y;     \
            v2 = silu_(acc[b][2] + b0) + xb.x; v3 = silu_(acc[b][3] + b1) + xb.y;     \
        }                                                                             \
        stsPairE(DH, DL, rowA * LDB + col, v0, v1);                                   \
        stsPairE(DH, DL, rowB * LDB + col, v2, v3);                                   \
    }                                                                                 \
    CP_WAIT0();                                                                       \
    __syncthreads();                                                                  \
} while (0)

    mma_stage_r(strip, h, lane, 4, ThU, TlU, WhU, WlU, acc);
    EPI_R(0, 0, Vh, Vl, g_Wph, g_Wpl, WB);
    mma_stage_r(strip, h, lane, 8, VhU, VlU, WhU, WlU, acc);
    EPI_R(1, 0, Th, Tl, g_Wph + 128 * LDB, g_Wpl + 128 * LDB, WB);
    mma_stage_r(strip, h, lane, 8, ThU, TlU, WhU, WlU, acc);
    EPI_R(2, 128, Vh, Vl, g_Wph + 2 * 128 * LDB, g_Wpl + 2 * 128 * LDB, WB);
    mma_stage_r(strip, h, lane, 8, VhU, VlU, WhU, WlU, acc);
    EPI_R(3, 256, Vh, Vl, g_Wph + 3 * 128 * LDB, g_Wpl + 3 * 128 * LDB, WB);
    mma_stage_r(strip, h, lane, 8, VhU, VlU, WhU, WlU, acc);
    EPI_R(1, 384, Th, Tl, g_Wph + 4 * 128 * LDB, g_Wpl + 4 * 128 * LDB, WB);
    mma_stage_r(strip, h, lane, 8, ThU, TlU, WhU, WlU, acc);
    EPI_R(2, 512, Vh, Vl, g_Wph + 5 * 128 * LDB, g_Wpl + 5 * 128 * LDB, WB);
    mma_stage_r(strip, h, lane, 8, VhU, VlU, WhU, WlU, acc);
    EPI_R(1, 640, Th, Tl, g_Wph + 6 * 128 * LDB, g_Wpl + 6 * 128 * LDB, WB);
    mma_stage_r(strip, h, lane, 8, ThU, TlU, WhU, WlU, acc);
    EPI_R(2, 768, Vh, Vl, (const __nv_bfloat16*)0, (const __nv_bfloat16*)0, 0);

    for (int i = tid; i < 768; i += 512) F[i] = Wr_g[i];
    for (int i = tid; i < 768; i += 512) {
        int r = i / 6, q = i - 6 * r;
        int rw = tile0 + r;
        F[768 + i] = (rw < E) ? rbf0[(size_t)rw * 6 + q] : 0.f;
    }
    __syncthreads();

    for (int i = tid; i < 128 * 32; i += 512) {
        int rr = i >> 5, cbl = (i & 31) * 4;
        int gr = tile0 + rr;
        if (gr >= E) continue;
        float2 p0 = ldPairE(Vh, Vl, rr * LDB + cbl);
        float2 p1 = ldPairE(Vh, Vl, rr * LDB + cbl + 2);
        float rv[6];
#pragma unroll
        for (int q = 0; q < 6; q++) rv[q] = F[768 + rr * 6 + q];
        float e1v[4] = {p0.x, p0.y, p1.x, p1.y};
        float e2v[4];
#pragma unroll
        for (int u = 0; u < 4; u++) {
            float f = 0.f;
#pragma unroll
            for (int q = 0; q < 6; q++) f += rv[q] * F[q * 128 + cbl + u];
            e2v[u] = f * e1v[u];
        }
        *(float4*)&out[(size_t)gr * 128 + cbl] = make_float4(e1v[0], e1v[1], e1v[2], e1v[3]);
        *(float4*)&out[((size_t)E + gr) * 128 + cbl] = make_float4(e2v[0], e2v[1], e2v[2], e2v[3]);
    }
}

extern "C" void kernel_launch(void* const* d_in, const int* in_sizes, int n_in,
                              void* d_out, int out_size) {
    const float* x1    = (const float*)d_in[0];
    const float* rbf0  = (const float*)d_in[1];
    const float* sbf   = (const float*)d_in[2];
    const float* tb    = (const float*)d_in[3];
    const int* idx_kj  = (const int*)d_in[4];
    const int* idx_ji  = (const int*)d_in[5];
    const float* W_rbf1 = (const float*)d_in[6];
    const float* W_rbf2 = (const float*)d_in[7];
    const float* W_sbf1 = (const float*)d_in[8];
    const float* W_sbf2 = (const float*)d_in[9];
    const float* W_t1   = (const float*)d_in[10];
    const float* W_t2   = (const float*)d_in[11];
    const float* W_rbf  = (const float*)d_in[12];
    const float* W_kj   = (const float*)d_in[13];
    const float* b_kj   = (const float*)d_in[14];
    const float* W_ji   = (const float*)d_in[15];
    const float* b_ji   = (const float*)d_in[16];
    const float* W_down = (const float*)d_in[17];
    const float* W_up   = (const float*)d_in[18];
    const float* rbW1   = (const float*)d_in[19];
    const float* rbb1   = (const float*)d_in[20];
    const float* rbW2   = (const float*)d_in[21];
    const float* rbb2   = (const float*)d_in[22];
    const float* W_lin  = (const float*)d_in[23];
    const float* b_lin  = (const float*)d_in[24];
    const float* raW1   = (const float*)d_in[25];
    const float* rab1   = (const float*)d_in[26];
    const float* raW2   = (const float*)d_in[27];
    const float* rab2   = (const float*)d_in[28];
    float* out = (float*)d_out;

    const int E = in_sizes[0] / 128;
    const int T = in_sizes[4];
    const int etiles = (E + 127) / 128;
    const int nchunks = (T + 31) / 32;
    const int nprep = 10 * 128 * LDB + 64 * LDB;
    const int nprep2 = 304 * 16 + 48 * 16;

    cudaFuncSetAttribute(k_pre_wmma, cudaFuncAttributeMaxDynamicSharedMemorySize, SM_PRE);
    cudaFuncSetAttribute(k_triplet,  cudaFuncAttributeMaxDynamicSharedMemorySize, SM_TRI);
    cudaFuncSetAttribute(k_post_mma, cudaFuncAttributeMaxDynamicSharedMemorySize, SM_POST);

    k_wcomb<<<3, 256>>>(W_rbf1, W_rbf2);
    k_wprep<<<(nprep + 255) / 256, 256>>>(rbW1, rbW2, W_lin, raW1, raW2, W_up, W_ji, W_kj, W_down);
    k_wprep2<<<(nprep2 + 255) / 256, 256>>>(W_t1, W_sbf1);
    k_pre_wmma<<<etiles, 512, SM_PRE>>>(x1, rbf0, b_ji, b_kj, E);
    k_triplet<<<296, 256, SM_TRI>>>(sbf, tb, idx_kj, idx_ji, W_sbf2, W_t2, T, nchunks);
    k_post_mma<<<etiles, 512, SM_POST>>>(x1, rbf0, W_rbf, rbb1, rbb2, b_lin, rab1, rab2, out, E);
}